// round 1
// baseline (speedup 1.0000x reference)
#include <cuda_runtime.h>
#include <math.h>

#define EMBED  512
#define NHEADS 8
#define HDIM   64
#define BATCH  4
#define SEQ    2048
#define MTOT   (BATCH*SEQ)   // 8192

// Scratch (device globals — no runtime allocation)
__device__ float g_q[BATCH*NHEADS*SEQ*HDIM];   // 16 MB
__device__ float g_k[BATCH*NHEADS*SEQ*HDIM];   // 16 MB
__device__ float g_v[BATCH*NHEADS*SEQ*HDIM];   // 16 MB
__device__ float g_o[BATCH*SEQ*EMBED];         // 16 MB

__device__ __forceinline__ float gelu_f(float x) {
    return 0.5f * x * (1.0f + erff(x * 0.70710678118654752440f));
}

// C = gelu(A @ W^T + bias)
// A: [M, 512] row-major. W: [512, 512] row-major ([N,K] => NT gemm).
// SPLIT=true : write to [B, H, S, D] layout (for q/k/v)
// SPLIT=false: write to [M, 512] flat (final output)
template<bool SPLIT>
__global__ __launch_bounds__(256)
void gemm_bias_gelu(const float* __restrict__ A, const float* __restrict__ W,
                    const float* __restrict__ bias, float* __restrict__ C) {
    const int K = EMBED;
    __shared__ float As[32][68];   // transposed: As[k][m], padded
    __shared__ float Ws[32][68];   // transposed: Ws[k][n], padded

    const int t  = threadIdx.x;
    const int tx = t & 15;         // n direction (16)
    const int ty = t >> 4;         // m direction (16)
    const int m0 = blockIdx.y * 64;
    const int n0 = blockIdx.x * 64;

    const int lr  = t >> 3;        // 0..31  (tile row for loads)
    const int lc4 = t & 7;         // 0..7   (float4 k-col for loads)

    float acc[4][4];
    #pragma unroll
    for (int i = 0; i < 4; ++i)
        #pragma unroll
        for (int j = 0; j < 4; ++j) acc[i][j] = 0.0f;

    for (int k0 = 0; k0 < K; k0 += 32) {
        #pragma unroll
        for (int rr = lr; rr < 64; rr += 32) {
            float4 av = *(const float4*)(A + (size_t)(m0 + rr) * K + k0 + lc4 * 4);
            As[lc4*4+0][rr] = av.x;
            As[lc4*4+1][rr] = av.y;
            As[lc4*4+2][rr] = av.z;
            As[lc4*4+3][rr] = av.w;
            float4 wv = *(const float4*)(W + (size_t)(n0 + rr) * K + k0 + lc4 * 4);
            Ws[lc4*4+0][rr] = wv.x;
            Ws[lc4*4+1][rr] = wv.y;
            Ws[lc4*4+2][rr] = wv.z;
            Ws[lc4*4+3][rr] = wv.w;
        }
        __syncthreads();

        #pragma unroll
        for (int kk = 0; kk < 32; ++kk) {
            float4 a = *(const float4*)&As[kk][ty * 4];
            float4 w = *(const float4*)&Ws[kk][tx * 4];
            acc[0][0] += a.x * w.x; acc[0][1] += a.x * w.y; acc[0][2] += a.x * w.z; acc[0][3] += a.x * w.w;
            acc[1][0] += a.y * w.x; acc[1][1] += a.y * w.y; acc[1][2] += a.y * w.z; acc[1][3] += a.y * w.w;
            acc[2][0] += a.z * w.x; acc[2][1] += a.z * w.y; acc[2][2] += a.z * w.z; acc[2][3] += a.z * w.w;
            acc[3][0] += a.w * w.x; acc[3][1] += a.w * w.y; acc[3][2] += a.w * w.z; acc[3][3] += a.w * w.w;
        }
        __syncthreads();
    }

    const int nb = n0 + tx * 4;
    float b0 = bias[nb + 0], b1 = bias[nb + 1], b2 = bias[nb + 2], b3 = bias[nb + 3];

    #pragma unroll
    for (int i = 0; i < 4; ++i) {
        int m = m0 + ty * 4 + i;
        float4 r;
        r.x = gelu_f(acc[i][0] + b0);
        r.y = gelu_f(acc[i][1] + b1);
        r.z = gelu_f(acc[i][2] + b2);
        r.w = gelu_f(acc[i][3] + b3);
        float* dst;
        if (SPLIT) {
            int b = m / SEQ, s = m % SEQ;
            int h = nb / HDIM, d = nb % HDIM;
            dst = C + (((size_t)(b * NHEADS + h) * SEQ + s) * HDIM + d);
        } else {
            dst = C + (size_t)m * EMBED + nb;
        }
        *(float4*)dst = r;
    }
}

// Flash attention, fp32. Q,K,V: [B*H, S, 64]. O written into [B, S, E] layout.
// Block: one (b,h) x 64-query tile. 256 threads: row = t/4 (64 rows),
// quad lane qd = t&3 owns 8 score cols and 16 output dims.
__global__ __launch_bounds__(256)
void flash_attn(const float* __restrict__ Q, const float* __restrict__ K,
                const float* __restrict__ V, float* __restrict__ O) {
    __shared__ float sq[64][68];
    __shared__ float sk[32][68];
    __shared__ float sv[32][68];
    __shared__ float sp[64][36];

    const int t  = threadIdx.x;
    const int bh = blockIdx.y;
    const int qt = blockIdx.x;

    const float* qbase = Q + ((size_t)bh * SEQ + qt * 64) * HDIM;
    for (int i = t; i < 64 * 16; i += 256) {
        int r = i >> 4, c4 = i & 15;
        *(float4*)&sq[r][c4 * 4] = *(const float4*)(qbase + r * HDIM + c4 * 4);
    }

    const int r  = t >> 2;
    const int qd = t & 3;

    float m_i = -1e30f, l_i = 0.0f;
    float acc[16];
    #pragma unroll
    for (int j = 0; j < 16; ++j) acc[j] = 0.0f;

    for (int kt = 0; kt < SEQ / 32; ++kt) {
        __syncthreads();   // protect sk/sv/sp reuse (and first-iter q load)
        const float* kb = K + ((size_t)bh * SEQ + kt * 32) * HDIM;
        const float* vb = V + ((size_t)bh * SEQ + kt * 32) * HDIM;
        for (int i = t; i < 32 * 16; i += 256) {
            int rr = i >> 4, c4 = i & 15;
            *(float4*)&sk[rr][c4 * 4] = *(const float4*)(kb + rr * HDIM + c4 * 4);
            *(float4*)&sv[rr][c4 * 4] = *(const float4*)(vb + rr * HDIM + c4 * 4);
        }
        __syncthreads();

        float s[8];
        #pragma unroll
        for (int cc = 0; cc < 8; ++cc) s[cc] = 0.0f;
        #pragma unroll
        for (int d4 = 0; d4 < 16; ++d4) {
            float4 qv = *(const float4*)&sq[r][d4 * 4];
            #pragma unroll
            for (int cc = 0; cc < 8; ++cc) {
                float4 kv = *(const float4*)&sk[qd * 8 + cc][d4 * 4];
                s[cc] += qv.x * kv.x + qv.y * kv.y + qv.z * kv.z + qv.w * kv.w;
            }
        }

        float mx = -1e30f;
        #pragma unroll
        for (int cc = 0; cc < 8; ++cc) { s[cc] *= 0.125f; mx = fmaxf(mx, s[cc]); }
        mx = fmaxf(mx, __shfl_xor_sync(0xffffffffu, mx, 1));
        mx = fmaxf(mx, __shfl_xor_sync(0xffffffffu, mx, 2));
        float m_new = fmaxf(m_i, mx);
        float corr  = __expf(m_i - m_new);

        float rs = 0.0f;
        #pragma unroll
        for (int cc = 0; cc < 8; ++cc) {
            float p = __expf(s[cc] - m_new);
            s[cc] = p;
            rs += p;
        }
        rs += __shfl_xor_sync(0xffffffffu, rs, 1);
        rs += __shfl_xor_sync(0xffffffffu, rs, 2);
        l_i = l_i * corr + rs;
        m_i = m_new;

        #pragma unroll
        for (int cc = 0; cc < 8; ++cc) sp[r][qd * 8 + cc] = s[cc];
        #pragma unroll
        for (int j = 0; j < 16; ++j) acc[j] *= corr;
        __syncthreads();

        #pragma unroll
        for (int c = 0; c < 32; ++c) {
            float p = sp[r][c];
            #pragma unroll
            for (int j4 = 0; j4 < 4; ++j4) {
                float4 vv = *(const float4*)&sv[c][qd * 16 + j4 * 4];
                acc[j4 * 4 + 0] += p * vv.x;
                acc[j4 * 4 + 1] += p * vv.y;
                acc[j4 * 4 + 2] += p * vv.z;
                acc[j4 * 4 + 3] += p * vv.w;
            }
        }
    }

    float inv = 1.0f / l_i;
    int b = bh >> 3, h = bh & 7;
    int s_idx = qt * 64 + r;
    float* op = O + (size_t)(b * SEQ + s_idx) * EMBED + h * HDIM + qd * 16;
    #pragma unroll
    for (int j4 = 0; j4 < 4; ++j4) {
        float4 o4;
        o4.x = acc[j4 * 4 + 0] * inv;
        o4.y = acc[j4 * 4 + 1] * inv;
        o4.z = acc[j4 * 4 + 2] * inv;
        o4.w = acc[j4 * 4 + 3] * inv;
        *(float4*)(op + j4 * 4) = o4;
    }
}

extern "C" void kernel_launch(void* const* d_in, const int* in_sizes, int n_in,
                              void* d_out, int out_size) {
    const float* x  = (const float*)d_in[0];
    const float* Wq = (const float*)d_in[1];
    const float* bq = (const float*)d_in[2];
    const float* Wk = (const float*)d_in[3];
    const float* bk = (const float*)d_in[4];
    const float* Wv = (const float*)d_in[5];
    const float* bv = (const float*)d_in[6];
    const float* Wo = (const float*)d_in[7];
    const float* bo = (const float*)d_in[8];
    float* out = (float*)d_out;

    float *gq, *gk, *gv, *go;
    cudaGetSymbolAddress((void**)&gq, g_q);
    cudaGetSymbolAddress((void**)&gk, g_k);
    cudaGetSymbolAddress((void**)&gv, g_v);
    cudaGetSymbolAddress((void**)&go, g_o);

    dim3 gridP(EMBED / 64, MTOT / 64);   // (8, 128)
    gemm_bias_gelu<true><<<gridP, 256>>>(x, Wq, bq, gq);
    gemm_bias_gelu<true><<<gridP, 256>>>(x, Wk, bk, gk);
    gemm_bias_gelu<true><<<gridP, 256>>>(x, Wv, bv, gv);

    dim3 gridA(SEQ / 64, BATCH * NHEADS);  // (32, 32)
    flash_attn<<<gridA, 256>>>(gq, gk, gv, go);

    gemm_bias_gelu<false><<<gridP, 256>>>(go, Wo, bo, out);
}

// round 2
// speedup vs baseline: 9.8743x; 9.8743x over previous
#include <cuda_runtime.h>
#include <math.h>
#include <stdint.h>

#define EMBED  512
#define NHEADS 8
#define HDIM   64
#define BATCH  4
#define SEQ    2048
#define MTOT   (BATCH*SEQ)   // 8192

// Scratch (device globals — no runtime allocation)
__device__ float g_q[BATCH*NHEADS*SEQ*HDIM];   // 16 MB
__device__ float g_k[BATCH*NHEADS*SEQ*HDIM];   // 16 MB
__device__ float g_v[BATCH*NHEADS*SEQ*HDIM];   // 16 MB
__device__ float g_o[BATCH*SEQ*EMBED];         // 16 MB

__device__ __forceinline__ float gelu_f(float x) {
    return 0.5f * x * (1.0f + erff(x * 0.70710678118654752440f));
}

__device__ __forceinline__ uint32_t f2tf(float f) {
    uint32_t u;
    asm("cvt.rna.tf32.f32 %0, %1;" : "=r"(u) : "f"(f));
    return u;
}

__device__ __forceinline__ void mma_tf32(float c[4], const uint32_t a[4], const uint32_t b[2]) {
    asm volatile(
        "mma.sync.aligned.m16n8k8.row.col.f32.tf32.tf32.f32 "
        "{%0,%1,%2,%3},{%4,%5,%6,%7},{%8,%9},{%0,%1,%2,%3};"
        : "+f"(c[0]), "+f"(c[1]), "+f"(c[2]), "+f"(c[3])
        : "r"(a[0]), "r"(a[1]), "r"(a[2]), "r"(a[3]), "r"(b[0]), "r"(b[1]));
}

// ---------------------------------------------------------------------------
// C = gelu(A @ W^T + bias).  A:[M,512], W:[512(N),512(K)] row-major.
// Block tile 128x64, 8 warps (4m x 2n), warp tile 32x32, BK=32. TF32 mma.
// ---------------------------------------------------------------------------
template<bool SPLIT>
__global__ __launch_bounds__(256)
void gemm_mma(const float* __restrict__ A, const float* __restrict__ W,
              const float* __restrict__ bias, float* __restrict__ C) {
    __shared__ uint32_t As[128][36];  // [m][k], stride 36 => 4m+k banks distinct
    __shared__ uint32_t Ws[64][36];   // [n][k]

    const int t    = threadIdx.x;
    const int lane = t & 31;
    const int warp = t >> 5;
    const int wm   = warp >> 1;       // 0..3
    const int wn   = warp & 1;        // 0..1
    const int m0   = blockIdx.y * 128;
    const int n0   = blockIdx.x * 64;
    const int r    = lane >> 2;       // 0..7
    const int cc   = lane & 3;        // 0..3

    const int lrow = t >> 3;          // 0..31
    const int lc4  = t & 7;           // 0..7

    float acc[2][4][4];
    #pragma unroll
    for (int mi = 0; mi < 2; ++mi)
        #pragma unroll
        for (int ni = 0; ni < 4; ++ni)
            #pragma unroll
            for (int j = 0; j < 4; ++j) acc[mi][ni][j] = 0.0f;

    for (int k0 = 0; k0 < EMBED; k0 += 32) {
        #pragma unroll
        for (int rr = 0; rr < 4; ++rr) {
            int m = lrow + rr * 32;
            float4 v = *(const float4*)(A + (size_t)(m0 + m) * EMBED + k0 + lc4 * 4);
            As[m][lc4 * 4 + 0] = f2tf(v.x);
            As[m][lc4 * 4 + 1] = f2tf(v.y);
            As[m][lc4 * 4 + 2] = f2tf(v.z);
            As[m][lc4 * 4 + 3] = f2tf(v.w);
        }
        #pragma unroll
        for (int rr = 0; rr < 2; ++rr) {
            int n = lrow + rr * 32;
            float4 v = *(const float4*)(W + (size_t)(n0 + n) * EMBED + k0 + lc4 * 4);
            Ws[n][lc4 * 4 + 0] = f2tf(v.x);
            Ws[n][lc4 * 4 + 1] = f2tf(v.y);
            Ws[n][lc4 * 4 + 2] = f2tf(v.z);
            Ws[n][lc4 * 4 + 3] = f2tf(v.w);
        }
        __syncthreads();

        #pragma unroll
        for (int k8 = 0; k8 < 4; ++k8) {
            uint32_t a[2][4], b[4][2];
            #pragma unroll
            for (int mi = 0; mi < 2; ++mi) {
                int mb = wm * 32 + mi * 16;
                a[mi][0] = As[mb + r][k8 * 8 + cc];
                a[mi][1] = As[mb + r + 8][k8 * 8 + cc];
                a[mi][2] = As[mb + r][k8 * 8 + cc + 4];
                a[mi][3] = As[mb + r + 8][k8 * 8 + cc + 4];
            }
            #pragma unroll
            for (int ni = 0; ni < 4; ++ni) {
                int nb = wn * 32 + ni * 8;
                b[ni][0] = Ws[nb + r][k8 * 8 + cc];
                b[ni][1] = Ws[nb + r][k8 * 8 + cc + 4];
            }
            #pragma unroll
            for (int mi = 0; mi < 2; ++mi)
                #pragma unroll
                for (int ni = 0; ni < 4; ++ni)
                    mma_tf32(acc[mi][ni], a[mi], b[ni]);
        }
        __syncthreads();
    }

    // Epilogue: bias + gelu, store
    #pragma unroll
    for (int mi = 0; mi < 2; ++mi) {
        #pragma unroll
        for (int ni = 0; ni < 4; ++ni) {
            int row = m0 + wm * 32 + mi * 16 + r;
            int col = n0 + wn * 32 + ni * 8 + 2 * cc;
            float b0 = bias[col], b1 = bias[col + 1];
            float2 v0, v1;
            v0.x = gelu_f(acc[mi][ni][0] + b0);
            v0.y = gelu_f(acc[mi][ni][1] + b1);
            v1.x = gelu_f(acc[mi][ni][2] + b0);
            v1.y = gelu_f(acc[mi][ni][3] + b1);
            if (SPLIT) {
                int bb = row >> 11, s = row & (SEQ - 1);
                int h = col >> 6, d = col & 63;
                float* dst0 = C + (((size_t)(bb * NHEADS + h) * SEQ + s) * HDIM + d);
                float* dst1 = C + (((size_t)(bb * NHEADS + h) * SEQ + (s + 8)) * HDIM + d);
                // row+8 same b (rows within a 16-row frag never cross batch: m0 multiple of 128)
                *(float2*)dst0 = v0;
                *(float2*)dst1 = v1;
            } else {
                *(float2*)(C + (size_t)row * EMBED + col)       = v0;
                *(float2*)(C + (size_t)(row + 8) * EMBED + col) = v1;
            }
        }
    }
}

// ---------------------------------------------------------------------------
// Flash attention, TF32 mma. Q,K,V: [B*H, S, 64]. O -> [B, S, E].
// 128 threads = 4 warps; warp w owns 16 query rows. KV tile = 64.
// P aliases the K-tile smem (phase-separated by a block sync).
// ---------------------------------------------------------------------------
__global__ __launch_bounds__(128)
void flash_mma(const float* __restrict__ Q, const float* __restrict__ K,
               const float* __restrict__ V, float* __restrict__ O) {
    __shared__ uint32_t sk[64][68];   // [kv][d], stride 68 => 4j+d conflict-free
    __shared__ uint32_t sv[64][72];   // [kv][d], stride 72 => 8k+n conflict-free
    uint32_t (*sp)[68] = sk;          // P aliases K tile

    const int t    = threadIdx.x;
    const int lane = t & 31;
    const int w    = t >> 5;
    const int bh   = blockIdx.y;
    const int qt   = blockIdx.x;
    const int r    = lane >> 2;
    const int cc   = lane & 3;

    // Q fragments in registers (d = 64 -> 8 k-frags)
    uint32_t qf[8][4];
    const float* qb = Q + ((size_t)bh * SEQ + qt * 64 + w * 16) * HDIM;
    #pragma unroll
    for (int kf = 0; kf < 8; ++kf) {
        qf[kf][0] = f2tf(qb[(size_t)r * HDIM + kf * 8 + cc]);
        qf[kf][1] = f2tf(qb[(size_t)(r + 8) * HDIM + kf * 8 + cc]);
        qf[kf][2] = f2tf(qb[(size_t)r * HDIM + kf * 8 + cc + 4]);
        qf[kf][3] = f2tf(qb[(size_t)(r + 8) * HDIM + kf * 8 + cc + 4]);
    }

    float o[8][4];
    #pragma unroll
    for (int nf = 0; nf < 8; ++nf)
        #pragma unroll
        for (int j = 0; j < 4; ++j) o[nf][j] = 0.0f;
    float m_i[2] = {-1e30f, -1e30f};
    float l_i[2] = {0.0f, 0.0f};

    for (int kt = 0; kt < SEQ / 64; ++kt) {
        __syncthreads();   // everyone done with sp(=sk)/sv from previous tile
        const float* kb = K + ((size_t)bh * SEQ + kt * 64) * HDIM;
        const float* vb = V + ((size_t)bh * SEQ + kt * 64) * HDIM;
        for (int i = t; i < 64 * 16; i += 128) {
            int rr = i >> 4, c4 = i & 15;
            float4 kv = *(const float4*)(kb + (size_t)rr * HDIM + c4 * 4);
            sk[rr][c4 * 4 + 0] = f2tf(kv.x);
            sk[rr][c4 * 4 + 1] = f2tf(kv.y);
            sk[rr][c4 * 4 + 2] = f2tf(kv.z);
            sk[rr][c4 * 4 + 3] = f2tf(kv.w);
            float4 vv = *(const float4*)(vb + (size_t)rr * HDIM + c4 * 4);
            sv[rr][c4 * 4 + 0] = f2tf(vv.x);
            sv[rr][c4 * 4 + 1] = f2tf(vv.y);
            sv[rr][c4 * 4 + 2] = f2tf(vv.z);
            sv[rr][c4 * 4 + 3] = f2tf(vv.w);
        }
        __syncthreads();

        // S = Q @ K^T  (scores for 16 q rows x 64 kv cols per warp)
        float s[8][4];
        #pragma unroll
        for (int nf = 0; nf < 8; ++nf)
            #pragma unroll
            for (int j = 0; j < 4; ++j) s[nf][j] = 0.0f;

        #pragma unroll
        for (int kf = 0; kf < 8; ++kf) {
            #pragma unroll
            for (int nf = 0; nf < 8; ++nf) {
                uint32_t b[2];
                b[0] = sk[nf * 8 + r][kf * 8 + cc];
                b[1] = sk[nf * 8 + r][kf * 8 + cc + 4];
                mma_tf32(s[nf], qf[kf], b);
            }
        }

        // Online softmax (rows r and r+8 per thread)
        float mx0 = -1e30f, mx1 = -1e30f;
        #pragma unroll
        for (int nf = 0; nf < 8; ++nf) {
            s[nf][0] *= 0.125f; s[nf][1] *= 0.125f;
            s[nf][2] *= 0.125f; s[nf][3] *= 0.125f;
            mx0 = fmaxf(mx0, fmaxf(s[nf][0], s[nf][1]));
            mx1 = fmaxf(mx1, fmaxf(s[nf][2], s[nf][3]));
        }
        mx0 = fmaxf(mx0, __shfl_xor_sync(0xffffffffu, mx0, 1));
        mx0 = fmaxf(mx0, __shfl_xor_sync(0xffffffffu, mx0, 2));
        mx1 = fmaxf(mx1, __shfl_xor_sync(0xffffffffu, mx1, 1));
        mx1 = fmaxf(mx1, __shfl_xor_sync(0xffffffffu, mx1, 2));

        float mn0 = fmaxf(m_i[0], mx0);
        float mn1 = fmaxf(m_i[1], mx1);
        float corr0 = __expf(m_i[0] - mn0);
        float corr1 = __expf(m_i[1] - mn1);

        float rs0 = 0.0f, rs1 = 0.0f;
        #pragma unroll
        for (int nf = 0; nf < 8; ++nf) {
            s[nf][0] = __expf(s[nf][0] - mn0);
            s[nf][1] = __expf(s[nf][1] - mn0);
            s[nf][2] = __expf(s[nf][2] - mn1);
            s[nf][3] = __expf(s[nf][3] - mn1);
            rs0 += s[nf][0] + s[nf][1];
            rs1 += s[nf][2] + s[nf][3];
        }
        rs0 += __shfl_xor_sync(0xffffffffu, rs0, 1);
        rs0 += __shfl_xor_sync(0xffffffffu, rs0, 2);
        rs1 += __shfl_xor_sync(0xffffffffu, rs1, 1);
        rs1 += __shfl_xor_sync(0xffffffffu, rs1, 2);

        l_i[0] = l_i[0] * corr0 + rs0;
        l_i[1] = l_i[1] * corr1 + rs1;
        m_i[0] = mn0;
        m_i[1] = mn1;

        #pragma unroll
        for (int nf = 0; nf < 8; ++nf) {
            o[nf][0] *= corr0; o[nf][1] *= corr0;
            o[nf][2] *= corr1; o[nf][3] *= corr1;
        }

        __syncthreads();   // all warps done reading sk -> safe to overwrite with P

        // Write P (tf32 bits) into sp (aliases sk); each warp owns rows w*16..+15
        #pragma unroll
        for (int nf = 0; nf < 8; ++nf) {
            sp[w * 16 + r][nf * 8 + 2 * cc]         = f2tf(s[nf][0]);
            sp[w * 16 + r][nf * 8 + 2 * cc + 1]     = f2tf(s[nf][1]);
            sp[w * 16 + r + 8][nf * 8 + 2 * cc]     = f2tf(s[nf][2]);
            sp[w * 16 + r + 8][nf * 8 + 2 * cc + 1] = f2tf(s[nf][3]);
        }
        __syncwarp();

        // O += P @ V
        #pragma unroll
        for (int kf = 0; kf < 8; ++kf) {
            uint32_t a[4];
            a[0] = sp[w * 16 + r][kf * 8 + cc];
            a[1] = sp[w * 16 + r + 8][kf * 8 + cc];
            a[2] = sp[w * 16 + r][kf * 8 + cc + 4];
            a[3] = sp[w * 16 + r + 8][kf * 8 + cc + 4];
            #pragma unroll
            for (int nf = 0; nf < 8; ++nf) {
                uint32_t b[2];
                b[0] = sv[kf * 8 + cc][nf * 8 + r];
                b[1] = sv[kf * 8 + cc + 4][nf * 8 + r];
                mma_tf32(o[nf], a, b);
            }
        }
    }

    // Normalize + store into [B, S, E]
    float inv0 = 1.0f / l_i[0];
    float inv1 = 1.0f / l_i[1];
    int bb = bh >> 3, h = bh & 7;
    int row0 = qt * 64 + w * 16 + r;
    float* op0 = O + ((size_t)bb * SEQ + row0) * EMBED + h * HDIM;
    float* op1 = O + ((size_t)bb * SEQ + row0 + 8) * EMBED + h * HDIM;
    #pragma unroll
    for (int nf = 0; nf < 8; ++nf) {
        float2 v0, v1;
        v0.x = o[nf][0] * inv0; v0.y = o[nf][1] * inv0;
        v1.x = o[nf][2] * inv1; v1.y = o[nf][3] * inv1;
        *(float2*)(op0 + nf * 8 + 2 * cc) = v0;
        *(float2*)(op1 + nf * 8 + 2 * cc) = v1;
    }
}

extern "C" void kernel_launch(void* const* d_in, const int* in_sizes, int n_in,
                              void* d_out, int out_size) {
    const float* x  = (const float*)d_in[0];
    const float* Wq = (const float*)d_in[1];
    const float* bq = (const float*)d_in[2];
    const float* Wk = (const float*)d_in[3];
    const float* bk = (const float*)d_in[4];
    const float* Wv = (const float*)d_in[5];
    const float* bv = (const float*)d_in[6];
    const float* Wo = (const float*)d_in[7];
    const float* bo = (const float*)d_in[8];
    float* out = (float*)d_out;

    float *gq, *gk, *gv, *go;
    cudaGetSymbolAddress((void**)&gq, g_q);
    cudaGetSymbolAddress((void**)&gk, g_k);
    cudaGetSymbolAddress((void**)&gv, g_v);
    cudaGetSymbolAddress((void**)&go, g_o);

    dim3 gridP(EMBED / 64, MTOT / 128);   // (8, 64)
    gemm_mma<true><<<gridP, 256>>>(x, Wq, bq, gq);
    gemm_mma<true><<<gridP, 256>>>(x, Wk, bk, gk);
    gemm_mma<true><<<gridP, 256>>>(x, Wv, bv, gv);

    dim3 gridA(SEQ / 64, BATCH * NHEADS);  // (32, 32)
    flash_mma<<<gridA, 128>>>(gq, gk, gv, go);

    gemm_mma<false><<<gridP, 256>>>(go, Wo, bo, out);
}

// round 3
// speedup vs baseline: 11.8704x; 1.2022x over previous
#include <cuda_runtime.h>
#include <math.h>
#include <stdint.h>

#define EMBED  512
#define NHEADS 8
#define HDIM   64
#define BATCH  4
#define SEQ    2048
#define MTOT   (BATCH*SEQ)   // 8192

// Scratch (device globals — no runtime allocation)
__device__ float g_q[BATCH*NHEADS*SEQ*HDIM];   // [B,H,S,D] tf32-rounded
__device__ float g_k[BATCH*NHEADS*SEQ*HDIM];   // [B,H,S,D] tf32-rounded
__device__ float g_vt[BATCH*NHEADS*HDIM*SEQ];  // [B,H,D,S] tf32-rounded (transposed!)
__device__ float g_o[BATCH*SEQ*EMBED];         // [B,S,E] fp32

__device__ __forceinline__ float gelu_f(float x) {
    return 0.5f * x * (1.0f + erff(x * 0.70710678118654752440f));
}

__device__ __forceinline__ uint32_t f2tf(float f) {
    uint32_t u;
    asm("cvt.rna.tf32.f32 %0, %1;" : "=r"(u) : "f"(f));
    return u;
}

__device__ __forceinline__ float fexp2(float x) {
    float y;
    asm("ex2.approx.ftz.f32 %0, %1;" : "=f"(y) : "f"(x));
    return y;
}

__device__ __forceinline__ uint32_t sptr(const void* p) {
    return (uint32_t)__cvta_generic_to_shared(p);
}

__device__ __forceinline__ void mma_tf32(float c[4], const uint32_t a[4], const uint32_t b[2]) {
    asm volatile(
        "mma.sync.aligned.m16n8k8.row.col.f32.tf32.tf32.f32 "
        "{%0,%1,%2,%3},{%4,%5,%6,%7},{%8,%9},{%0,%1,%2,%3};"
        : "+f"(c[0]), "+f"(c[1]), "+f"(c[2]), "+f"(c[3])
        : "r"(a[0]), "r"(a[1]), "r"(a[2]), "r"(a[3]), "r"(b[0]), "r"(b[1]));
}

__device__ __forceinline__ void ldsm4(uint32_t r[4], uint32_t saddr) {
    asm volatile("ldmatrix.sync.aligned.m8n8.x4.shared.b16 {%0,%1,%2,%3}, [%4];"
                 : "=r"(r[0]), "=r"(r[1]), "=r"(r[2]), "=r"(r[3]) : "r"(saddr));
}

// ---------------------------------------------------------------------------
// C = gelu(A @ W^T + bias).  A:[M,512], W:[512(N),512(K)] row-major.
// Block tile 128x64, 8 warps (4m x 2n), warp tile 32x32, BK=32. TF32 mma.
// MODE 0: flat [M,512] fp32 (final output)
// MODE 1: [B,H,S,D] tf32-rounded (Q, K)
// MODE 2: [B,H,D,S] tf32-rounded transposed (V^T)
// ---------------------------------------------------------------------------
template<int MODE>
__global__ __launch_bounds__(256)
void gemm_mma(const float* __restrict__ A, const float* __restrict__ W,
              const float* __restrict__ bias, float* __restrict__ C) {
    __shared__ uint32_t As[128][36];  // [m][k], stride 36: 4m+k banks distinct
    __shared__ uint32_t Ws[64][36];   // [n][k]

    const int t    = threadIdx.x;
    const int lane = t & 31;
    const int warp = t >> 5;
    const int wm   = warp >> 1;       // 0..3
    const int wn   = warp & 1;        // 0..1
    const int m0   = blockIdx.y * 128;
    const int n0   = blockIdx.x * 64;
    const int r    = lane >> 2;       // 0..7
    const int cc   = lane & 3;        // 0..3

    const int lrow = t >> 3;          // 0..31
    const int lc4  = t & 7;           // 0..7

    // ldmatrix lane offsets (bytes)
    const uint32_t a_loff = (((lane & 15) * 36) + ((lane >> 4) * 4)) * 4;
    const uint32_t b_loff = ((((lane >> 4) * 8 + (lane & 7)) * 36) + (((lane >> 3) & 1) * 4)) * 4;
    const uint32_t as_w = sptr(&As[0][0]) + (uint32_t)(wm * 32 * 36) * 4 + a_loff;
    const uint32_t ws_w = sptr(&Ws[0][0]) + (uint32_t)(wn * 32 * 36) * 4 + b_loff;

    float acc[2][4][4];
    #pragma unroll
    for (int mi = 0; mi < 2; ++mi)
        #pragma unroll
        for (int ni = 0; ni < 4; ++ni)
            #pragma unroll
            for (int j = 0; j < 4; ++j) acc[mi][ni][j] = 0.0f;

    for (int k0 = 0; k0 < EMBED; k0 += 32) {
        #pragma unroll
        for (int rr = 0; rr < 4; ++rr) {
            int m = lrow + rr * 32;
            float4 v = *(const float4*)(A + (size_t)(m0 + m) * EMBED + k0 + lc4 * 4);
            As[m][lc4 * 4 + 0] = f2tf(v.x);
            As[m][lc4 * 4 + 1] = f2tf(v.y);
            As[m][lc4 * 4 + 2] = f2tf(v.z);
            As[m][lc4 * 4 + 3] = f2tf(v.w);
        }
        #pragma unroll
        for (int rr = 0; rr < 2; ++rr) {
            int n = lrow + rr * 32;
            float4 v = *(const float4*)(W + (size_t)(n0 + n) * EMBED + k0 + lc4 * 4);
            Ws[n][lc4 * 4 + 0] = f2tf(v.x);
            Ws[n][lc4 * 4 + 1] = f2tf(v.y);
            Ws[n][lc4 * 4 + 2] = f2tf(v.z);
            Ws[n][lc4 * 4 + 3] = f2tf(v.w);
        }
        __syncthreads();

        #pragma unroll
        for (int k8 = 0; k8 < 4; ++k8) {
            uint32_t a[2][4], b[2][4];
            ldsm4(a[0], as_w + k8 * 32);
            ldsm4(a[1], as_w + 16 * 36 * 4 + k8 * 32);
            ldsm4(b[0], ws_w + k8 * 32);
            ldsm4(b[1], ws_w + 16 * 36 * 4 + k8 * 32);
            #pragma unroll
            for (int mi = 0; mi < 2; ++mi)
                #pragma unroll
                for (int np = 0; np < 2; ++np) {
                    mma_tf32(acc[mi][2 * np],     a[mi], &b[np][0]);
                    mma_tf32(acc[mi][2 * np + 1], a[mi], &b[np][2]);
                }
        }
        __syncthreads();
    }

    // Epilogue: bias + gelu, store
    #pragma unroll
    for (int mi = 0; mi < 2; ++mi) {
        #pragma unroll
        for (int ni = 0; ni < 4; ++ni) {
            int row = m0 + wm * 32 + mi * 16 + r;
            int col = n0 + wn * 32 + ni * 8 + 2 * cc;
            float b0 = bias[col], b1 = bias[col + 1];
            float e00 = gelu_f(acc[mi][ni][0] + b0);
            float e01 = gelu_f(acc[mi][ni][1] + b1);
            float e10 = gelu_f(acc[mi][ni][2] + b0);
            float e11 = gelu_f(acc[mi][ni][3] + b1);
            if (MODE == 0) {
                float2 v0 = {e00, e01}, v1 = {e10, e11};
                *(float2*)(C + (size_t)row * EMBED + col)       = v0;
                *(float2*)(C + (size_t)(row + 8) * EMBED + col) = v1;
            } else {
                // tf32-round for downstream attention
                float r00 = __uint_as_float(f2tf(e00));
                float r01 = __uint_as_float(f2tf(e01));
                float r10 = __uint_as_float(f2tf(e10));
                float r11 = __uint_as_float(f2tf(e11));
                int bb = row >> 11, s = row & (SEQ - 1);
                int h = col >> 6, d = col & 63;
                if (MODE == 1) {
                    float2 v0 = {r00, r01}, v1 = {r10, r11};
                    float* dst0 = C + (((size_t)(bb * NHEADS + h) * SEQ + s) * HDIM + d);
                    float* dst1 = C + (((size_t)(bb * NHEADS + h) * SEQ + (s + 8)) * HDIM + d);
                    *(float2*)dst0 = v0;
                    *(float2*)dst1 = v1;
                } else {
                    // MODE 2: V^T [B,H,D,S]
                    float* base = C + ((size_t)((bb * NHEADS + h) * HDIM + d)) * SEQ + s;
                    base[0]       = r00;   // (d,   s)
                    base[SEQ]     = r01;   // (d+1, s)
                    base[8]       = r10;   // (d,   s+8)
                    base[SEQ + 8] = r11;   // (d+1, s+8)
                }
            }
        }
    }
}

// ---------------------------------------------------------------------------
// Flash attention, TF32 mma + ldmatrix. Q,K: [B*H,S,64] rounded; Vt: [B*H,64,S].
// 128 threads = 4 warps; warp w owns 16 query rows. KV tile = 64.
// P aliases the K-tile smem (phase-separated by a block sync).
// ---------------------------------------------------------------------------
__global__ __launch_bounds__(128)
void flash_mma(const float* __restrict__ Q, const float* __restrict__ K,
               const float* __restrict__ Vt, float* __restrict__ O) {
    __shared__ uint32_t sk[64][68];   // [kv][d]
    __shared__ uint32_t svT[64][68];  // [d][kv]
    uint32_t (*sp)[68] = sk;          // P aliases K tile

    const int t    = threadIdx.x;
    const int lane = t & 31;
    const int w    = t >> 5;
    const int bh   = blockIdx.y;
    const int qt   = blockIdx.x;
    const int r    = lane >> 2;
    const int cc   = lane & 3;

    // ldmatrix lane offsets (bytes), stride 68
    const uint32_t b_loff = ((((lane >> 4) * 8 + (lane & 7)) * 68) + (((lane >> 3) & 1) * 4)) * 4;
    const uint32_t a_loff = (((lane & 15) * 68) + ((lane >> 4) * 4)) * 4;
    const uint32_t skb = sptr(&sk[0][0]) + b_loff;
    const uint32_t svb = sptr(&svT[0][0]) + b_loff;
    const uint32_t spa = sptr(&sk[0][0]) + (uint32_t)(w * 16 * 68) * 4 + a_loff;

    // Q fragments (already tf32-rounded in gmem) — registers for the whole kernel
    uint32_t qf[8][4];
    const float* qb = Q + ((size_t)bh * SEQ + qt * 64 + w * 16) * HDIM;
    #pragma unroll
    for (int kf = 0; kf < 8; ++kf) {
        qf[kf][0] = __float_as_uint(qb[(size_t)r * HDIM + kf * 8 + cc]);
        qf[kf][1] = __float_as_uint(qb[(size_t)(r + 8) * HDIM + kf * 8 + cc]);
        qf[kf][2] = __float_as_uint(qb[(size_t)r * HDIM + kf * 8 + cc + 4]);
        qf[kf][3] = __float_as_uint(qb[(size_t)(r + 8) * HDIM + kf * 8 + cc + 4]);
    }

    float o[8][4];
    #pragma unroll
    for (int nf = 0; nf < 8; ++nf)
        #pragma unroll
        for (int j = 0; j < 4; ++j) o[nf][j] = 0.0f;
    float m_i[2] = {-1e30f, -1e30f};   // in log2 domain
    float l_i[2] = {0.0f, 0.0f};

    const float SC = 0.18033688011112042f;  // (1/8) * log2(e)

    for (int kt = 0; kt < SEQ / 64; ++kt) {
        __syncthreads();   // everyone done with sp(=sk)/svT from previous tile
        const float* kb  = K  + ((size_t)bh * SEQ + kt * 64) * HDIM;
        const float* vtb = Vt + (size_t)bh * HDIM * SEQ + kt * 64;
        #pragma unroll
        for (int i = t; i < 64 * 16; i += 128) {
            int rr = i >> 4, c4 = i & 15;
            *(uint4*)&sk[rr][c4 * 4]  = *(const uint4*)(kb  + (size_t)rr * HDIM + c4 * 4);
            *(uint4*)&svT[rr][c4 * 4] = *(const uint4*)(vtb + (size_t)rr * SEQ  + c4 * 4);
        }
        __syncthreads();

        // S = Q @ K^T
        float s[8][4];
        #pragma unroll
        for (int nf = 0; nf < 8; ++nf)
            #pragma unroll
            for (int j = 0; j < 4; ++j) s[nf][j] = 0.0f;

        #pragma unroll
        for (int kf = 0; kf < 8; ++kf) {
            #pragma unroll
            for (int nfp = 0; nfp < 4; ++nfp) {
                uint32_t bb[4];
                ldsm4(bb, skb + (uint32_t)(nfp * 16 * 68) * 4 + kf * 32);
                mma_tf32(s[2 * nfp],     qf[kf], &bb[0]);
                mma_tf32(s[2 * nfp + 1], qf[kf], &bb[2]);
            }
        }

        // Online softmax in exp2 domain (rows r and r+8 per thread)
        float mx0 = -1e30f, mx1 = -1e30f;
        #pragma unroll
        for (int nf = 0; nf < 8; ++nf) {
            s[nf][0] *= SC; s[nf][1] *= SC;
            s[nf][2] *= SC; s[nf][3] *= SC;
            mx0 = fmaxf(mx0, fmaxf(s[nf][0], s[nf][1]));
            mx1 = fmaxf(mx1, fmaxf(s[nf][2], s[nf][3]));
        }
        mx0 = fmaxf(mx0, __shfl_xor_sync(0xffffffffu, mx0, 1));
        mx0 = fmaxf(mx0, __shfl_xor_sync(0xffffffffu, mx0, 2));
        mx1 = fmaxf(mx1, __shfl_xor_sync(0xffffffffu, mx1, 1));
        mx1 = fmaxf(mx1, __shfl_xor_sync(0xffffffffu, mx1, 2));

        float mn0 = fmaxf(m_i[0], mx0);
        float mn1 = fmaxf(m_i[1], mx1);
        float corr0 = fexp2(m_i[0] - mn0);
        float corr1 = fexp2(m_i[1] - mn1);

        float rs0 = 0.0f, rs1 = 0.0f;
        #pragma unroll
        for (int nf = 0; nf < 8; ++nf) {
            s[nf][0] = fexp2(s[nf][0] - mn0);
            s[nf][1] = fexp2(s[nf][1] - mn0);
            s[nf][2] = fexp2(s[nf][2] - mn1);
            s[nf][3] = fexp2(s[nf][3] - mn1);
            rs0 += s[nf][0] + s[nf][1];
            rs1 += s[nf][2] + s[nf][3];
        }
        rs0 += __shfl_xor_sync(0xffffffffu, rs0, 1);
        rs0 += __shfl_xor_sync(0xffffffffu, rs0, 2);
        rs1 += __shfl_xor_sync(0xffffffffu, rs1, 1);
        rs1 += __shfl_xor_sync(0xffffffffu, rs1, 2);

        l_i[0] = l_i[0] * corr0 + rs0;
        l_i[1] = l_i[1] * corr1 + rs1;
        m_i[0] = mn0;
        m_i[1] = mn1;

        #pragma unroll
        for (int nf = 0; nf < 8; ++nf) {
            o[nf][0] *= corr0; o[nf][1] *= corr0;
            o[nf][2] *= corr1; o[nf][3] *= corr1;
        }

        __syncthreads();   // all warps done reading sk -> safe to overwrite with P

        // Write P (tf32 bits) into sp (aliases sk); warp owns rows w*16..+15
        #pragma unroll
        for (int nf = 0; nf < 8; ++nf) {
            uint2 p01, p23;
            p01.x = f2tf(s[nf][0]); p01.y = f2tf(s[nf][1]);
            p23.x = f2tf(s[nf][2]); p23.y = f2tf(s[nf][3]);
            *(uint2*)&sp[w * 16 + r][nf * 8 + 2 * cc]     = p01;
            *(uint2*)&sp[w * 16 + r + 8][nf * 8 + 2 * cc] = p23;
        }
        __syncwarp();

        // O += P @ V  (V^T tile, same ldmatrix pattern as K)
        #pragma unroll
        for (int kf = 0; kf < 8; ++kf) {
            uint32_t aa[4];
            ldsm4(aa, spa + kf * 32);
            #pragma unroll
            for (int nfp = 0; nfp < 4; ++nfp) {
                uint32_t bb[4];
                ldsm4(bb, svb + (uint32_t)(nfp * 16 * 68) * 4 + kf * 32);
                mma_tf32(o[2 * nfp],     aa, &bb[0]);
                mma_tf32(o[2 * nfp + 1], aa, &bb[2]);
            }
        }
    }

    // Normalize + store into [B, S, E]
    float inv0 = 1.0f / l_i[0];
    float inv1 = 1.0f / l_i[1];
    int bb = bh >> 3, h = bh & 7;
    int row0 = qt * 64 + w * 16 + r;
    float* op0 = O + ((size_t)bb * SEQ + row0) * EMBED + h * HDIM;
    float* op1 = O + ((size_t)bb * SEQ + row0 + 8) * EMBED + h * HDIM;
    #pragma unroll
    for (int nf = 0; nf < 8; ++nf) {
        float2 v0, v1;
        v0.x = o[nf][0] * inv0; v0.y = o[nf][1] * inv0;
        v1.x = o[nf][2] * inv1; v1.y = o[nf][3] * inv1;
        *(float2*)(op0 + nf * 8 + 2 * cc) = v0;
        *(float2*)(op1 + nf * 8 + 2 * cc) = v1;
    }
}

extern "C" void kernel_launch(void* const* d_in, const int* in_sizes, int n_in,
                              void* d_out, int out_size) {
    const float* x  = (const float*)d_in[0];
    const float* Wq = (const float*)d_in[1];
    const float* bq = (const float*)d_in[2];
    const float* Wk = (const float*)d_in[3];
    const float* bk = (const float*)d_in[4];
    const float* Wv = (const float*)d_in[5];
    const float* bv = (const float*)d_in[6];
    const float* Wo = (const float*)d_in[7];
    const float* bo = (const float*)d_in[8];
    float* out = (float*)d_out;

    float *gq, *gk, *gvt, *go;
    cudaGetSymbolAddress((void**)&gq, g_q);
    cudaGetSymbolAddress((void**)&gk, g_k);
    cudaGetSymbolAddress((void**)&gvt, g_vt);
    cudaGetSymbolAddress((void**)&go, g_o);

    dim3 gridP(EMBED / 64, MTOT / 128);   // (8, 64)
    gemm_mma<1><<<gridP, 256>>>(x, Wq, bq, gq);
    gemm_mma<1><<<gridP, 256>>>(x, Wk, bk, gk);
    gemm_mma<2><<<gridP, 256>>>(x, Wv, bv, gvt);

    dim3 gridA(SEQ / 64, BATCH * NHEADS);  // (32, 32)
    flash_mma<<<gridA, 128>>>(gq, gk, gvt, go);

    gemm_mma<0><<<gridP, 256>>>(go, Wo, bo, out);
}

// round 4
// speedup vs baseline: 20.1976x; 1.7015x over previous
#include <cuda_runtime.h>
#include <cuda_fp16.h>
#include <math.h>
#include <stdint.h>

#define EMBED  512
#define NHEADS 8
#define HDIM   64
#define BATCH  4
#define SEQ    2048
#define MTOT   (BATCH*SEQ)   // 8192

// Scratch (device globals — no runtime allocation)
__device__ __half g_q[BATCH*NHEADS*SEQ*HDIM];   // [B,H,S,D] fp16
__device__ __half g_k[BATCH*NHEADS*SEQ*HDIM];   // [B,H,S,D] fp16
__device__ __half g_v[BATCH*NHEADS*SEQ*HDIM];   // [B,H,S,D] fp16
__device__ float  g_o[BATCH*SEQ*EMBED];         // [B,S,E] fp32

__device__ __forceinline__ float gelu_f(float x) {
    return 0.5f * x * (1.0f + erff(x * 0.70710678118654752440f));
}

__device__ __forceinline__ uint32_t packh(float a, float b) {
    __half2 h = __floats2half2_rn(a, b);
    return *(uint32_t*)&h;
}

__device__ __forceinline__ float fexp2(float x) {
    float y;
    asm("ex2.approx.ftz.f32 %0, %1;" : "=f"(y) : "f"(x));
    return y;
}

__device__ __forceinline__ uint32_t sptr(const void* p) {
    return (uint32_t)__cvta_generic_to_shared(p);
}

__device__ __forceinline__ void mma_f16(float c[4], const uint32_t a[4], const uint32_t b[2]) {
    asm volatile(
        "mma.sync.aligned.m16n8k16.row.col.f32.f16.f16.f32 "
        "{%0,%1,%2,%3},{%4,%5,%6,%7},{%8,%9},{%0,%1,%2,%3};"
        : "+f"(c[0]), "+f"(c[1]), "+f"(c[2]), "+f"(c[3])
        : "r"(a[0]), "r"(a[1]), "r"(a[2]), "r"(a[3]), "r"(b[0]), "r"(b[1]));
}

__device__ __forceinline__ void ldsm4(uint32_t r[4], uint32_t saddr) {
    asm volatile("ldmatrix.sync.aligned.m8n8.x4.shared.b16 {%0,%1,%2,%3}, [%4];"
                 : "=r"(r[0]), "=r"(r[1]), "=r"(r[2]), "=r"(r[3]) : "r"(saddr));
}

__device__ __forceinline__ void ldsm4t(uint32_t r[4], uint32_t saddr) {
    asm volatile("ldmatrix.sync.aligned.m8n8.x4.trans.shared.b16 {%0,%1,%2,%3}, [%4];"
                 : "=r"(r[0]), "=r"(r[1]), "=r"(r[2]), "=r"(r[3]) : "r"(saddr));
}

// ---------------------------------------------------------------------------
// C = gelu(A @ W^T + bias).  A:[M,512] fp32, W:[512(N),512(K)] fp32 row-major.
// Block tile 128x64, 8 warps (4m x 2n), warp tile 32x32, BK=32. FP16 mma.
// MODE 0: flat [M,512] fp32 (final output)
// MODE 1: [B,H,S,D] fp16 (Q, K, V)
// ---------------------------------------------------------------------------
template<int MODE>
__global__ __launch_bounds__(256)
void gemm_mma(const float* __restrict__ A, const float* __restrict__ W,
              const float* __restrict__ bias, void* __restrict__ Cout) {
    __shared__ uint32_t As[128][20];  // [m][kpair], stride 20 (20m mod 32 distinct)
    __shared__ uint32_t Ws[64][20];   // [n][kpair]

    const int t    = threadIdx.x;
    const int lane = t & 31;
    const int warp = t >> 5;
    const int wm   = warp >> 1;       // 0..3
    const int wn   = warp & 1;        // 0..1
    const int m0   = blockIdx.y * 128;
    const int n0   = blockIdx.x * 64;
    const int r    = lane >> 2;       // 0..7
    const int cc   = lane & 3;        // 0..3

    const int lrow = t >> 3;          // 0..31
    const int lc4  = t & 7;           // 0..7

    // ldmatrix lane offsets (bytes), stride 20 words
    const uint32_t a_loff = (((lane & 15) * 20) + ((lane >> 4) * 4)) * 4;
    const uint32_t b_loff = ((((lane & 7) + ((lane >> 4) * 8)) * 20) + (((lane >> 3) & 1) * 4)) * 4;
    const uint32_t as_w = sptr(&As[0][0]) + (uint32_t)(wm * 32 * 20) * 4 + a_loff;
    const uint32_t ws_w = sptr(&Ws[0][0]) + (uint32_t)(wn * 32 * 20) * 4 + b_loff;

    float acc[2][4][4];
    #pragma unroll
    for (int mi = 0; mi < 2; ++mi)
        #pragma unroll
        for (int ni = 0; ni < 4; ++ni)
            #pragma unroll
            for (int j = 0; j < 4; ++j) acc[mi][ni][j] = 0.0f;

    for (int k0 = 0; k0 < EMBED; k0 += 32) {
        #pragma unroll
        for (int rr = 0; rr < 4; ++rr) {
            int m = lrow + rr * 32;
            float4 v = *(const float4*)(A + (size_t)(m0 + m) * EMBED + k0 + lc4 * 4);
            uint2 p;
            p.x = packh(v.x, v.y);
            p.y = packh(v.z, v.w);
            *(uint2*)&As[m][lc4 * 2] = p;
        }
        #pragma unroll
        for (int rr = 0; rr < 2; ++rr) {
            int n = lrow + rr * 32;
            float4 v = *(const float4*)(W + (size_t)(n0 + n) * EMBED + k0 + lc4 * 4);
            uint2 p;
            p.x = packh(v.x, v.y);
            p.y = packh(v.z, v.w);
            *(uint2*)&Ws[n][lc4 * 2] = p;
        }
        __syncthreads();

        #pragma unroll
        for (int ks = 0; ks < 2; ++ks) {
            uint32_t a[2][4], b[2][4];
            ldsm4(a[0], as_w + ks * 32);
            ldsm4(a[1], as_w + 16 * 20 * 4 + ks * 32);
            ldsm4(b[0], ws_w + ks * 32);
            ldsm4(b[1], ws_w + 16 * 20 * 4 + ks * 32);
            #pragma unroll
            for (int mi = 0; mi < 2; ++mi)
                #pragma unroll
                for (int np = 0; np < 2; ++np) {
                    mma_f16(acc[mi][2 * np],     a[mi], &b[np][0]);
                    mma_f16(acc[mi][2 * np + 1], a[mi], &b[np][2]);
                }
        }
        __syncthreads();
    }

    // Epilogue: bias + gelu, store
    #pragma unroll
    for (int mi = 0; mi < 2; ++mi) {
        #pragma unroll
        for (int ni = 0; ni < 4; ++ni) {
            int row = m0 + wm * 32 + mi * 16 + r;
            int col = n0 + wn * 32 + ni * 8 + 2 * cc;
            float b0 = bias[col], b1 = bias[col + 1];
            float e00 = gelu_f(acc[mi][ni][0] + b0);
            float e01 = gelu_f(acc[mi][ni][1] + b1);
            float e10 = gelu_f(acc[mi][ni][2] + b0);
            float e11 = gelu_f(acc[mi][ni][3] + b1);
            if (MODE == 0) {
                float* C = (float*)Cout;
                float2 v0 = {e00, e01}, v1 = {e10, e11};
                *(float2*)(C + (size_t)row * EMBED + col)       = v0;
                *(float2*)(C + (size_t)(row + 8) * EMBED + col) = v1;
            } else {
                __half* C = (__half*)Cout;
                int bb = row >> 11, s = row & (SEQ - 1);
                int h = col >> 6, d = col & 63;
                *(uint32_t*)&C[(((size_t)(bb * NHEADS + h) * SEQ + s) * HDIM + d)]       = packh(e00, e01);
                *(uint32_t*)&C[(((size_t)(bb * NHEADS + h) * SEQ + (s + 8)) * HDIM + d)] = packh(e10, e11);
            }
        }
    }
}

// ---------------------------------------------------------------------------
// Flash attention, FP16 mma + ldmatrix. Q,K,V: [B*H,S,64] fp16.
// 128 threads = 4 warps; warp w owns 16 query rows. KV tile = 64.
// P (fp16) aliases the K-tile smem (phase-separated by a block sync).
// PV uses ldmatrix.trans on the row-major V tile (no transpose layout needed).
// ---------------------------------------------------------------------------
__global__ __launch_bounds__(128)
void flash_mma(const __half* __restrict__ Q, const __half* __restrict__ K,
               const __half* __restrict__ V, float* __restrict__ O) {
    __shared__ uint32_t sk[64][36];   // [kv][dpair], stride 36 (4m distinct banks)
    __shared__ uint32_t sv[64][36];   // [kv][dpair]
    uint32_t (*sp)[36] = sk;          // P [qrow][kvpair] aliases K tile

    const int t    = threadIdx.x;
    const int lane = t & 31;
    const int w    = t >> 5;
    const int bh   = blockIdx.y;
    const int qt   = blockIdx.x;
    const int r    = lane >> 2;
    const int cc   = lane & 3;

    // ldmatrix lane offsets (bytes), stride 36 words
    const uint32_t b_loff = ((((lane & 7) + ((lane >> 4) * 8)) * 36) + (((lane >> 3) & 1) * 4)) * 4;
    const uint32_t t_loff = (((lane & 15) * 36) + ((lane >> 4) * 4)) * 4;  // A-frag & trans-B
    const uint32_t skb = sptr(&sk[0][0]) + b_loff;
    const uint32_t svb = sptr(&sv[0][0]) + t_loff;
    const uint32_t spa = sptr(&sk[0][0]) + (uint32_t)(w * 16 * 36) * 4 + t_loff;

    // Q fragments (fp16 pairs straight from gmem) — registers for the whole kernel
    uint32_t qf[4][4];
    const __half* qb = Q + ((size_t)bh * SEQ + qt * 64 + w * 16) * HDIM;
    #pragma unroll
    for (int kf = 0; kf < 4; ++kf) {
        qf[kf][0] = *(const uint32_t*)&qb[(size_t)r * HDIM + kf * 16 + cc * 2];
        qf[kf][1] = *(const uint32_t*)&qb[(size_t)(r + 8) * HDIM + kf * 16 + cc * 2];
        qf[kf][2] = *(const uint32_t*)&qb[(size_t)r * HDIM + kf * 16 + 8 + cc * 2];
        qf[kf][3] = *(const uint32_t*)&qb[(size_t)(r + 8) * HDIM + kf * 16 + 8 + cc * 2];
    }

    float o[8][4];
    #pragma unroll
    for (int nf = 0; nf < 8; ++nf)
        #pragma unroll
        for (int j = 0; j < 4; ++j) o[nf][j] = 0.0f;
    float m_i[2] = {-1e30f, -1e30f};   // log2 domain
    float l_i[2] = {0.0f, 0.0f};

    const float SC = 0.18033688011112042f;  // (1/8) * log2(e)

    for (int kt = 0; kt < SEQ / 64; ++kt) {
        __syncthreads();   // everyone done with sp(=sk)/sv from previous tile
        const __half* kb = K + ((size_t)bh * SEQ + kt * 64) * HDIM;
        const __half* vb = V + ((size_t)bh * SEQ + kt * 64) * HDIM;
        #pragma unroll
        for (int i = t; i < 64 * 8; i += 128) {
            int rr = i >> 3, c4 = i & 7;
            *(uint4*)&sk[rr][c4 * 4] = *(const uint4*)(kb + (size_t)rr * HDIM + c4 * 8);
            *(uint4*)&sv[rr][c4 * 4] = *(const uint4*)(vb + (size_t)rr * HDIM + c4 * 8);
        }
        __syncthreads();

        // S = Q @ K^T
        float s[8][4];
        #pragma unroll
        for (int nf = 0; nf < 8; ++nf)
            #pragma unroll
            for (int j = 0; j < 4; ++j) s[nf][j] = 0.0f;

        #pragma unroll
        for (int kf = 0; kf < 4; ++kf) {
            #pragma unroll
            for (int nfp = 0; nfp < 4; ++nfp) {
                uint32_t bb[4];
                ldsm4(bb, skb + (uint32_t)(nfp * 16 * 36) * 4 + kf * 32);
                mma_f16(s[2 * nfp],     qf[kf], &bb[0]);
                mma_f16(s[2 * nfp + 1], qf[kf], &bb[2]);
            }
        }

        // Online softmax in exp2 domain (rows r and r+8 per thread)
        float mx0 = -1e30f, mx1 = -1e30f;
        #pragma unroll
        for (int nf = 0; nf < 8; ++nf) {
            s[nf][0] *= SC; s[nf][1] *= SC;
            s[nf][2] *= SC; s[nf][3] *= SC;
            mx0 = fmaxf(mx0, fmaxf(s[nf][0], s[nf][1]));
            mx1 = fmaxf(mx1, fmaxf(s[nf][2], s[nf][3]));
        }
        mx0 = fmaxf(mx0, __shfl_xor_sync(0xffffffffu, mx0, 1));
        mx0 = fmaxf(mx0, __shfl_xor_sync(0xffffffffu, mx0, 2));
        mx1 = fmaxf(mx1, __shfl_xor_sync(0xffffffffu, mx1, 1));
        mx1 = fmaxf(mx1, __shfl_xor_sync(0xffffffffu, mx1, 2));

        float mn0 = fmaxf(m_i[0], mx0);
        float mn1 = fmaxf(m_i[1], mx1);
        float corr0 = fexp2(m_i[0] - mn0);
        float corr1 = fexp2(m_i[1] - mn1);

        float rs0 = 0.0f, rs1 = 0.0f;
        #pragma unroll
        for (int nf = 0; nf < 8; ++nf) {
            s[nf][0] = fexp2(s[nf][0] - mn0);
            s[nf][1] = fexp2(s[nf][1] - mn0);
            s[nf][2] = fexp2(s[nf][2] - mn1);
            s[nf][3] = fexp2(s[nf][3] - mn1);
            rs0 += s[nf][0] + s[nf][1];
            rs1 += s[nf][2] + s[nf][3];
        }
        rs0 += __shfl_xor_sync(0xffffffffu, rs0, 1);
        rs0 += __shfl_xor_sync(0xffffffffu, rs0, 2);
        rs1 += __shfl_xor_sync(0xffffffffu, rs1, 1);
        rs1 += __shfl_xor_sync(0xffffffffu, rs1, 2);

        l_i[0] = l_i[0] * corr0 + rs0;
        l_i[1] = l_i[1] * corr1 + rs1;
        m_i[0] = mn0;
        m_i[1] = mn1;

        #pragma unroll
        for (int nf = 0; nf < 8; ++nf) {
            o[nf][0] *= corr0; o[nf][1] *= corr0;
            o[nf][2] *= corr1; o[nf][3] *= corr1;
        }

        __syncthreads();   // all warps done reading sk -> safe to overwrite with P

        // Write P (fp16 pairs) into sp (aliases sk); warp owns rows w*16..+15
        #pragma unroll
        for (int nf = 0; nf < 8; ++nf) {
            sp[w * 16 + r][nf * 4 + cc]     = packh(s[nf][0], s[nf][1]);
            sp[w * 16 + r + 8][nf * 4 + cc] = packh(s[nf][2], s[nf][3]);
        }
        __syncwarp();

        // O += P @ V  (row-major V tile, B-frags via ldmatrix.trans)
        #pragma unroll
        for (int kf = 0; kf < 4; ++kf) {
            uint32_t aa[4];
            ldsm4(aa, spa + kf * 32);
            #pragma unroll
            for (int nfp = 0; nfp < 4; ++nfp) {
                uint32_t bb[4];
                ldsm4t(bb, svb + (uint32_t)(kf * 16 * 36) * 4 + nfp * 32);
                mma_f16(o[2 * nfp],     aa, &bb[0]);
                mma_f16(o[2 * nfp + 1], aa, &bb[2]);
            }
        }
    }

    // Normalize + store into [B, S, E]
    float inv0 = 1.0f / l_i[0];
    float inv1 = 1.0f / l_i[1];
    int bb = bh >> 3, h = bh & 7;
    int row0 = qt * 64 + w * 16 + r;
    float* op0 = O + ((size_t)bb * SEQ + row0) * EMBED + h * HDIM;
    float* op1 = O + ((size_t)bb * SEQ + row0 + 8) * EMBED + h * HDIM;
    #pragma unroll
    for (int nf = 0; nf < 8; ++nf) {
        float2 v0, v1;
        v0.x = o[nf][0] * inv0; v0.y = o[nf][1] * inv0;
        v1.x = o[nf][2] * inv1; v1.y = o[nf][3] * inv1;
        *(float2*)(op0 + nf * 8 + 2 * cc) = v0;
        *(float2*)(op1 + nf * 8 + 2 * cc) = v1;
    }
}

extern "C" void kernel_launch(void* const* d_in, const int* in_sizes, int n_in,
                              void* d_out, int out_size) {
    const float* x  = (const float*)d_in[0];
    const float* Wq = (const float*)d_in[1];
    const float* bq = (const float*)d_in[2];
    const float* Wk = (const float*)d_in[3];
    const float* bk = (const float*)d_in[4];
    const float* Wv = (const float*)d_in[5];
    const float* bv = (const float*)d_in[6];
    const float* Wo = (const float*)d_in[7];
    const float* bo = (const float*)d_in[8];
    float* out = (float*)d_out;

    __half *gq, *gk, *gv;
    float *go;
    cudaGetSymbolAddress((void**)&gq, g_q);
    cudaGetSymbolAddress((void**)&gk, g_k);
    cudaGetSymbolAddress((void**)&gv, g_v);
    cudaGetSymbolAddress((void**)&go, g_o);

    dim3 gridP(EMBED / 64, MTOT / 128);   // (8, 64)
    gemm_mma<1><<<gridP, 256>>>(x, Wq, bq, gq);
    gemm_mma<1><<<gridP, 256>>>(x, Wk, bk, gk);
    gemm_mma<1><<<gridP, 256>>>(x, Wv, bv, gv);

    dim3 gridA(SEQ / 64, BATCH * NHEADS);  // (32, 32)
    flash_mma<<<gridA, 128>>>(gq, gk, gv, go);

    gemm_mma<0><<<gridP, 256>>>(go, Wo, bo, out);
}

// round 6
// speedup vs baseline: 22.2290x; 1.1006x over previous
#include <cuda_runtime.h>
#include <cuda_fp16.h>
#include <math.h>
#include <stdint.h>

#define EMBED  512
#define NHEADS 8
#define HDIM   64
#define BATCH  4
#define SEQ    2048
#define MTOT   (BATCH*SEQ)   // 8192

// Scratch (device globals — no runtime allocation)
__device__ __half g_q[BATCH*NHEADS*SEQ*HDIM];   // [B,H,S,D] fp16
__device__ __half g_k[BATCH*NHEADS*SEQ*HDIM];   // [B,H,S,D] fp16
__device__ __half g_v[BATCH*NHEADS*SEQ*HDIM];   // [B,H,S,D] fp16
__device__ __half g_o[BATCH*SEQ*EMBED];         // [B,S,E] fp16

__device__ __forceinline__ float gelu_f(float x) {
    return 0.5f * x * (1.0f + erff(x * 0.70710678118654752440f));
}

__device__ __forceinline__ uint32_t packh(float a, float b) {
    __half2 h = __floats2half2_rn(a, b);
    return *(uint32_t*)&h;
}

__device__ __forceinline__ float fexp2(float x) {
    float y;
    asm("ex2.approx.ftz.f32 %0, %1;" : "=f"(y) : "f"(x));
    return y;
}

__device__ __forceinline__ uint32_t sptr(const void* p) {
    return (uint32_t)__cvta_generic_to_shared(p);
}

__device__ __forceinline__ void mma_f16(float c[4], const uint32_t a[4], const uint32_t b[2]) {
    asm volatile(
        "mma.sync.aligned.m16n8k16.row.col.f32.f16.f16.f32 "
        "{%0,%1,%2,%3},{%4,%5,%6,%7},{%8,%9},{%0,%1,%2,%3};"
        : "+f"(c[0]), "+f"(c[1]), "+f"(c[2]), "+f"(c[3])
        : "r"(a[0]), "r"(a[1]), "r"(a[2]), "r"(a[3]), "r"(b[0]), "r"(b[1]));
}

__device__ __forceinline__ void ldsm4(uint32_t r[4], uint32_t saddr) {
    asm volatile("ldmatrix.sync.aligned.m8n8.x4.shared.b16 {%0,%1,%2,%3}, [%4];"
                 : "=r"(r[0]), "=r"(r[1]), "=r"(r[2]), "=r"(r[3]) : "r"(saddr));
}

__device__ __forceinline__ void ldsm4t(uint32_t r[4], uint32_t saddr) {
    asm volatile("ldmatrix.sync.aligned.m8n8.x4.trans.shared.b16 {%0,%1,%2,%3}, [%4];"
                 : "=r"(r[0]), "=r"(r[1]), "=r"(r[2]), "=r"(r[3]) : "r"(saddr));
}

// ---------------------------------------------------------------------------
// GEMM core: C = gelu(A @ W^T + bias). Block tile 128x128, 8 warps (2m x 4n),
// warp tile 64x32, BK=32, fp16 mma, pipelined gmem->reg prefetch.
// AHALF: A is fp16 [M,512]. else fp32.
// OHALF: out is fp16 [B,H,S,D]; else fp32 flat [M,512].
// Each thread stages one (row, 16-elem k-chunk): arow = t>>1, koff = (t&1)*16.
// ---------------------------------------------------------------------------
template<bool AHALF, bool OHALF>
__device__ __forceinline__ void gemm_core(const void* Ap, const float* __restrict__ W,
                                          const float* __restrict__ bias, void* Cout,
                                          uint32_t (*As)[20], uint32_t (*Ws)[20]) {
    const int t    = threadIdx.x;
    const int lane = t & 31;
    const int warp = t >> 5;
    const int wm   = warp >> 2;       // 0..1
    const int wn   = warp & 3;        // 0..3
    const int m0   = blockIdx.y * 128;
    const int n0   = blockIdx.x * 128;
    const int r    = lane >> 2;       // 0..7
    const int cc   = lane & 3;        // 0..3

    const int arow = t >> 1;          // 0..127
    const int koff = (t & 1) * 16;    // k element offset (16 elements per thread)

    const uint32_t a_loff = (((lane & 15) * 20) + ((lane >> 4) * 4)) * 4;
    const uint32_t b_loff = ((((lane & 7) + ((lane >> 4) * 8)) * 20) + (((lane >> 3) & 1) * 4)) * 4;
    const uint32_t as_w = sptr(&As[0][0]) + (uint32_t)(wm * 64 * 20) * 4 + a_loff;
    const uint32_t ws_w = sptr(&Ws[0][0]) + (uint32_t)(wn * 32 * 20) * 4 + b_loff;

    float acc[4][4][4];
    #pragma unroll
    for (int mi = 0; mi < 4; ++mi)
        #pragma unroll
        for (int ni = 0; ni < 4; ++ni)
            #pragma unroll
            for (int j = 0; j < 4; ++j) acc[mi][ni][j] = 0.0f;

    const float*  Af = (const float*)Ap;
    const __half* Ah = (const __half*)Ap;

    float4 ra[4]; uint4 rah[2];
    float4 rw[4];
    // prefetch k0 = 0
    if (AHALF) {
        rah[0] = *(const uint4*)(Ah + (size_t)(m0 + arow) * EMBED + koff);       // 8 halves
        rah[1] = *(const uint4*)(Ah + (size_t)(m0 + arow) * EMBED + koff + 8);   // 8 halves
    } else {
        #pragma unroll
        for (int j = 0; j < 4; ++j)
            ra[j] = *(const float4*)(Af + (size_t)(m0 + arow) * EMBED + koff + j * 4);
    }
    #pragma unroll
    for (int j = 0; j < 4; ++j)
        rw[j] = *(const float4*)(W + (size_t)(n0 + arow) * EMBED + koff + j * 4);

    for (int k0 = 0; k0 < EMBED; k0 += 32) {
        // store staged regs to smem (convert if fp32)
        if (AHALF) {
            *(uint4*)&As[arow][(koff >> 1) + 0] = rah[0];
            *(uint4*)&As[arow][(koff >> 1) + 4] = rah[1];
        } else {
            #pragma unroll
            for (int j = 0; j < 4; ++j) {
                uint2 p;
                p.x = packh(ra[j].x, ra[j].y);
                p.y = packh(ra[j].z, ra[j].w);
                *(uint2*)&As[arow][(koff >> 1) + j * 2] = p;
            }
        }
        #pragma unroll
        for (int j = 0; j < 4; ++j) {
            uint2 p;
            p.x = packh(rw[j].x, rw[j].y);
            p.y = packh(rw[j].z, rw[j].w);
            *(uint2*)&Ws[arow][(koff >> 1) + j * 2] = p;
        }
        __syncthreads();

        // prefetch next k-slab while mma runs
        if (k0 + 32 < EMBED) {
            if (AHALF) {
                rah[0] = *(const uint4*)(Ah + (size_t)(m0 + arow) * EMBED + k0 + 32 + koff);
                rah[1] = *(const uint4*)(Ah + (size_t)(m0 + arow) * EMBED + k0 + 32 + koff + 8);
            } else {
                #pragma unroll
                for (int j = 0; j < 4; ++j)
                    ra[j] = *(const float4*)(Af + (size_t)(m0 + arow) * EMBED + k0 + 32 + koff + j * 4);
            }
            #pragma unroll
            for (int j = 0; j < 4; ++j)
                rw[j] = *(const float4*)(W + (size_t)(n0 + arow) * EMBED + k0 + 32 + koff + j * 4);
        }

        #pragma unroll
        for (int ks = 0; ks < 2; ++ks) {
            uint32_t a[4][4], b[2][4];
            #pragma unroll
            for (int mi = 0; mi < 4; ++mi)
                ldsm4(a[mi], as_w + (uint32_t)(mi * 16 * 20) * 4 + ks * 32);
            #pragma unroll
            for (int np = 0; np < 2; ++np)
                ldsm4(b[np], ws_w + (uint32_t)(np * 16 * 20) * 4 + ks * 32);
            #pragma unroll
            for (int mi = 0; mi < 4; ++mi)
                #pragma unroll
                for (int np = 0; np < 2; ++np) {
                    mma_f16(acc[mi][2 * np],     a[mi], &b[np][0]);
                    mma_f16(acc[mi][2 * np + 1], a[mi], &b[np][2]);
                }
        }
        __syncthreads();
    }

    // Epilogue: bias + gelu, store
    #pragma unroll
    for (int mi = 0; mi < 4; ++mi) {
        #pragma unroll
        for (int ni = 0; ni < 4; ++ni) {
            int row = m0 + wm * 64 + mi * 16 + r;
            int col = n0 + wn * 32 + ni * 8 + 2 * cc;
            float b0 = bias[col], b1 = bias[col + 1];
            float e00 = gelu_f(acc[mi][ni][0] + b0);
            float e01 = gelu_f(acc[mi][ni][1] + b1);
            float e10 = gelu_f(acc[mi][ni][2] + b0);
            float e11 = gelu_f(acc[mi][ni][3] + b1);
            if (!OHALF) {
                float* C = (float*)Cout;
                float2 v0 = {e00, e01}, v1 = {e10, e11};
                *(float2*)(C + (size_t)row * EMBED + col)       = v0;
                *(float2*)(C + (size_t)(row + 8) * EMBED + col) = v1;
            } else {
                __half* C = (__half*)Cout;
                int bb = row >> 11, s = row & (SEQ - 1);
                int h = col >> 6, d = col & 63;
                *(uint32_t*)&C[(((size_t)(bb * NHEADS + h) * SEQ + s) * HDIM + d)]       = packh(e00, e01);
                *(uint32_t*)&C[(((size_t)(bb * NHEADS + h) * SEQ + (s + 8)) * HDIM + d)] = packh(e10, e11);
            }
        }
    }
}

// Fused Q/K/V projection: blockIdx.z selects which projection.
__global__ __launch_bounds__(256)
void qkv_proj(const float* __restrict__ x,
              const float* __restrict__ Wq, const float* __restrict__ bq,
              const float* __restrict__ Wk, const float* __restrict__ bk,
              const float* __restrict__ Wv, const float* __restrict__ bv) {
    __shared__ uint32_t As[128][20];
    __shared__ uint32_t Ws[128][20];
    const int z = blockIdx.z;
    const float* W    = (z == 0) ? Wq : (z == 1) ? Wk : Wv;
    const float* bias = (z == 0) ? bq : (z == 1) ? bk : bv;
    __half* C         = (z == 0) ? g_q : (z == 1) ? g_k : g_v;
    gemm_core<false, true>(x, W, bias, C, As, Ws);
}

__global__ __launch_bounds__(256)
void out_proj(const float* __restrict__ Wo, const float* __restrict__ bo,
              float* __restrict__ out) {
    __shared__ uint32_t As[128][20];
    __shared__ uint32_t Ws[128][20];
    gemm_core<true, false>(g_o, Wo, bo, out, As, Ws);
}

// ---------------------------------------------------------------------------
// Flash attention, FP16 mma + ldmatrix. Q,K,V: [B*H,S,64] fp16, O: [B,S,E] fp16.
// 128 threads = 4 warps; warp w owns 32 query rows (2 m-frags). KV tile = 64.
// P has its own smem (per-warp region => only __syncwarp between QK and PV).
// ---------------------------------------------------------------------------
__global__ __launch_bounds__(128)
void flash_mma(const __half* __restrict__ Q, const __half* __restrict__ K,
               const __half* __restrict__ V, __half* __restrict__ O) {
    __shared__ uint32_t sk[64][36];    // [kv][dpair]
    __shared__ uint32_t sv[64][36];    // [kv][dpair]
    __shared__ uint32_t sp[128][36];   // [qrow][kvpair]

    const int t    = threadIdx.x;
    const int lane = t & 31;
    const int w    = t >> 5;
    const int bh   = blockIdx.y;
    const int qt   = blockIdx.x;
    const int r    = lane >> 2;
    const int cc   = lane & 3;

    const uint32_t b_loff = ((((lane & 7) + ((lane >> 4) * 8)) * 36) + (((lane >> 3) & 1) * 4)) * 4;
    const uint32_t t_loff = (((lane & 15) * 36) + ((lane >> 4) * 4)) * 4;
    const uint32_t skb = sptr(&sk[0][0]) + b_loff;
    const uint32_t svb = sptr(&sv[0][0]) + t_loff;
    const uint32_t spa = sptr(&sp[0][0]) + (uint32_t)(w * 32 * 36) * 4 + t_loff;

    // Q fragments (fp16 pairs from gmem) — registers for the whole kernel
    uint32_t qf[2][4][4];
    const __half* qb = Q + ((size_t)bh * SEQ + qt * 128 + w * 32) * HDIM;
    #pragma unroll
    for (int mi = 0; mi < 2; ++mi) {
        #pragma unroll
        for (int kf = 0; kf < 4; ++kf) {
            int row0 = mi * 16 + r;
            qf[mi][kf][0] = *(const uint32_t*)&qb[(size_t)row0 * HDIM + kf * 16 + cc * 2];
            qf[mi][kf][1] = *(const uint32_t*)&qb[(size_t)(row0 + 8) * HDIM + kf * 16 + cc * 2];
            qf[mi][kf][2] = *(const uint32_t*)&qb[(size_t)row0 * HDIM + kf * 16 + 8 + cc * 2];
            qf[mi][kf][3] = *(const uint32_t*)&qb[(size_t)(row0 + 8) * HDIM + kf * 16 + 8 + cc * 2];
        }
    }

    float o[2][8][4];
    #pragma unroll
    for (int mi = 0; mi < 2; ++mi)
        #pragma unroll
        for (int nf = 0; nf < 8; ++nf)
            #pragma unroll
            for (int j = 0; j < 4; ++j) o[mi][nf][j] = 0.0f;
    float m_i[2][2] = {{-1e30f, -1e30f}, {-1e30f, -1e30f}};   // log2 domain
    float l_i[2][2] = {{0.0f, 0.0f}, {0.0f, 0.0f}};

    const float SC = 0.18033688011112042f;  // (1/8) * log2(e)

    for (int kt = 0; kt < SEQ / 64; ++kt) {
        __syncthreads();   // everyone done with sk/sv from previous tile
        const __half* kb = K + ((size_t)bh * SEQ + kt * 64) * HDIM;
        const __half* vb = V + ((size_t)bh * SEQ + kt * 64) * HDIM;
        #pragma unroll
        for (int i = t; i < 64 * 8; i += 128) {
            int rr = i >> 3, c4 = i & 7;
            *(uint4*)&sk[rr][c4 * 4] = *(const uint4*)(kb + (size_t)rr * HDIM + c4 * 8);
            *(uint4*)&sv[rr][c4 * 4] = *(const uint4*)(vb + (size_t)rr * HDIM + c4 * 8);
        }
        __syncthreads();

        // S = Q @ K^T : 32 q rows x 64 kv cols per warp
        float s[2][8][4];
        #pragma unroll
        for (int mi = 0; mi < 2; ++mi)
            #pragma unroll
            for (int nf = 0; nf < 8; ++nf)
                #pragma unroll
                for (int j = 0; j < 4; ++j) s[mi][nf][j] = 0.0f;

        #pragma unroll
        for (int kf = 0; kf < 4; ++kf) {
            #pragma unroll
            for (int nfp = 0; nfp < 4; ++nfp) {
                uint32_t bb[4];
                ldsm4(bb, skb + (uint32_t)(nfp * 16 * 36) * 4 + kf * 32);
                #pragma unroll
                for (int mi = 0; mi < 2; ++mi) {
                    mma_f16(s[mi][2 * nfp],     qf[mi][kf], &bb[0]);
                    mma_f16(s[mi][2 * nfp + 1], qf[mi][kf], &bb[2]);
                }
            }
        }

        // Online softmax in exp2 domain, per m-frag
        #pragma unroll
        for (int mi = 0; mi < 2; ++mi) {
            float mx0 = -1e30f, mx1 = -1e30f;
            #pragma unroll
            for (int nf = 0; nf < 8; ++nf) {
                s[mi][nf][0] *= SC; s[mi][nf][1] *= SC;
                s[mi][nf][2] *= SC; s[mi][nf][3] *= SC;
                mx0 = fmaxf(mx0, fmaxf(s[mi][nf][0], s[mi][nf][1]));
                mx1 = fmaxf(mx1, fmaxf(s[mi][nf][2], s[mi][nf][3]));
            }
            mx0 = fmaxf(mx0, __shfl_xor_sync(0xffffffffu, mx0, 1));
            mx0 = fmaxf(mx0, __shfl_xor_sync(0xffffffffu, mx0, 2));
            mx1 = fmaxf(mx1, __shfl_xor_sync(0xffffffffu, mx1, 1));
            mx1 = fmaxf(mx1, __shfl_xor_sync(0xffffffffu, mx1, 2));

            float mn0 = fmaxf(m_i[mi][0], mx0);
            float mn1 = fmaxf(m_i[mi][1], mx1);
            float corr0 = fexp2(m_i[mi][0] - mn0);
            float corr1 = fexp2(m_i[mi][1] - mn1);

            float rs0 = 0.0f, rs1 = 0.0f;
            #pragma unroll
            for (int nf = 0; nf < 8; ++nf) {
                s[mi][nf][0] = fexp2(s[mi][nf][0] - mn0);
                s[mi][nf][1] = fexp2(s[mi][nf][1] - mn0);
                s[mi][nf][2] = fexp2(s[mi][nf][2] - mn1);
                s[mi][nf][3] = fexp2(s[mi][nf][3] - mn1);
                rs0 += s[mi][nf][0] + s[mi][nf][1];
                rs1 += s[mi][nf][2] + s[mi][nf][3];
            }
            rs0 += __shfl_xor_sync(0xffffffffu, rs0, 1);
            rs0 += __shfl_xor_sync(0xffffffffu, rs0, 2);
            rs1 += __shfl_xor_sync(0xffffffffu, rs1, 1);
            rs1 += __shfl_xor_sync(0xffffffffu, rs1, 2);

            l_i[mi][0] = l_i[mi][0] * corr0 + rs0;
            l_i[mi][1] = l_i[mi][1] * corr1 + rs1;
            m_i[mi][0] = mn0;
            m_i[mi][1] = mn1;

            #pragma unroll
            for (int nf = 0; nf < 8; ++nf) {
                o[mi][nf][0] *= corr0; o[mi][nf][1] *= corr0;
                o[mi][nf][2] *= corr1; o[mi][nf][3] *= corr1;
            }

            // Write P (fp16 pairs): warp-private rows
            #pragma unroll
            for (int nf = 0; nf < 8; ++nf) {
                sp[w * 32 + mi * 16 + r][nf * 4 + cc]     = packh(s[mi][nf][0], s[mi][nf][1]);
                sp[w * 32 + mi * 16 + r + 8][nf * 4 + cc] = packh(s[mi][nf][2], s[mi][nf][3]);
            }
        }
        __syncwarp();

        // O += P @ V  (row-major V tile, B-frags via ldmatrix.trans)
        #pragma unroll
        for (int kf = 0; kf < 4; ++kf) {
            uint32_t aa[2][4];
            #pragma unroll
            for (int mi = 0; mi < 2; ++mi)
                ldsm4(aa[mi], spa + (uint32_t)(mi * 16 * 36) * 4 + kf * 32);
            #pragma unroll
            for (int nfp = 0; nfp < 4; ++nfp) {
                uint32_t bb[4];
                ldsm4t(bb, svb + (uint32_t)(kf * 16 * 36) * 4 + nfp * 32);
                #pragma unroll
                for (int mi = 0; mi < 2; ++mi) {
                    mma_f16(o[mi][2 * nfp],     aa[mi], &bb[0]);
                    mma_f16(o[mi][2 * nfp + 1], aa[mi], &bb[2]);
                }
            }
        }
    }

    // Normalize + store fp16 into [B, S, E]
    int bb = bh >> 3, h = bh & 7;
    #pragma unroll
    for (int mi = 0; mi < 2; ++mi) {
        float inv0 = 1.0f / l_i[mi][0];
        float inv1 = 1.0f / l_i[mi][1];
        int row0 = qt * 128 + w * 32 + mi * 16 + r;
        __half* op0 = O + ((size_t)bb * SEQ + row0) * EMBED + h * HDIM;
        __half* op1 = O + ((size_t)bb * SEQ + row0 + 8) * EMBED + h * HDIM;
        #pragma unroll
        for (int nf = 0; nf < 8; ++nf) {
            *(uint32_t*)(op0 + nf * 8 + 2 * cc) = packh(o[mi][nf][0] * inv0, o[mi][nf][1] * inv0);
            *(uint32_t*)(op1 + nf * 8 + 2 * cc) = packh(o[mi][nf][2] * inv1, o[mi][nf][3] * inv1);
        }
    }
}

extern "C" void kernel_launch(void* const* d_in, const int* in_sizes, int n_in,
                              void* d_out, int out_size) {
    const float* x  = (const float*)d_in[0];
    const float* Wq = (const float*)d_in[1];
    const float* bq = (const float*)d_in[2];
    const float* Wk = (const float*)d_in[3];
    const float* bk = (const float*)d_in[4];
    const float* Wv = (const float*)d_in[5];
    const float* bv = (const float*)d_in[6];
    const float* Wo = (const float*)d_in[7];
    const float* bo = (const float*)d_in[8];
    float* out = (float*)d_out;

    __half *gq, *gk, *gv, *go;
    cudaGetSymbolAddress((void**)&gq, g_q);
    cudaGetSymbolAddress((void**)&gk, g_k);
    cudaGetSymbolAddress((void**)&gv, g_v);
    cudaGetSymbolAddress((void**)&go, g_o);

    dim3 gridP(EMBED / 128, MTOT / 128, 3);   // (4, 64, 3)
    qkv_proj<<<gridP, 256>>>(x, Wq, bq, Wk, bk, Wv, bv);

    dim3 gridA(SEQ / 128, BATCH * NHEADS);    // (16, 32)
    flash_mma<<<gridA, 128>>>(gq, gk, gv, go);

    dim3 gridO(EMBED / 128, MTOT / 128);      // (4, 64)
    out_proj<<<gridO, 256>>>(Wo, bo, out);
}

// round 7
// speedup vs baseline: 27.1787x; 1.2227x over previous
#include <cuda_runtime.h>
#include <cuda_fp16.h>
#include <math.h>
#include <stdint.h>

#define EMBED  512
#define NHEADS 8
#define HDIM   64
#define BATCH  4
#define SEQ    2048
#define MTOT   (BATCH*SEQ)   // 8192

// Scratch (device globals — no runtime allocation)
__device__ __half g_xh[MTOT*EMBED];             // x in fp16
__device__ __half g_wh[4*EMBED*EMBED];          // Wq,Wk,Wv,Wo in fp16
__device__ __half g_q[BATCH*NHEADS*SEQ*HDIM];   // [B,H,S,D] fp16
__device__ __half g_k[BATCH*NHEADS*SEQ*HDIM];   // [B,H,S,D] fp16
__device__ __half g_v[BATCH*NHEADS*SEQ*HDIM];   // [B,H,S,D] fp16
__device__ __half g_o[BATCH*SEQ*EMBED];         // [B,S,E] fp16

__device__ __forceinline__ float gelu_f(float x) {
    return 0.5f * x * (1.0f + erff(x * 0.70710678118654752440f));
}

__device__ __forceinline__ uint32_t packh(float a, float b) {
    __half2 h = __floats2half2_rn(a, b);
    return *(uint32_t*)&h;
}

__device__ __forceinline__ float fexp2(float x) {
    float y;
    asm("ex2.approx.ftz.f32 %0, %1;" : "=f"(y) : "f"(x));
    return y;
}

__device__ __forceinline__ uint32_t sptr(const void* p) {
    return (uint32_t)__cvta_generic_to_shared(p);
}

__device__ __forceinline__ void cpasync16(uint32_t dst, const void* src) {
    asm volatile("cp.async.ca.shared.global [%0], [%1], 16;" :: "r"(dst), "l"(src));
}
__device__ __forceinline__ void cp_commit() {
    asm volatile("cp.async.commit_group;");
}
template<int N>
__device__ __forceinline__ void cp_wait() {
    asm volatile("cp.async.wait_group %0;" :: "n"(N));
}

__device__ __forceinline__ void mma_f16(float c[4], const uint32_t a[4], const uint32_t b[2]) {
    asm volatile(
        "mma.sync.aligned.m16n8k16.row.col.f32.f16.f16.f32 "
        "{%0,%1,%2,%3},{%4,%5,%6,%7},{%8,%9},{%0,%1,%2,%3};"
        : "+f"(c[0]), "+f"(c[1]), "+f"(c[2]), "+f"(c[3])
        : "r"(a[0]), "r"(a[1]), "r"(a[2]), "r"(a[3]), "r"(b[0]), "r"(b[1]));
}

__device__ __forceinline__ void ldsm4(uint32_t r[4], uint32_t saddr) {
    asm volatile("ldmatrix.sync.aligned.m8n8.x4.shared.b16 {%0,%1,%2,%3}, [%4];"
                 : "=r"(r[0]), "=r"(r[1]), "=r"(r[2]), "=r"(r[3]) : "r"(saddr));
}

__device__ __forceinline__ void ldsm4t(uint32_t r[4], uint32_t saddr) {
    asm volatile("ldmatrix.sync.aligned.m8n8.x4.trans.shared.b16 {%0,%1,%2,%3}, [%4];"
                 : "=r"(r[0]), "=r"(r[1]), "=r"(r[2]), "=r"(r[3]) : "r"(saddr));
}

// ---------------------------------------------------------------------------
// Convert x and all four weight matrices to fp16 (one memory-bound pass).
// ---------------------------------------------------------------------------
__global__ __launch_bounds__(256)
void convert_f2h(const float* __restrict__ x,
                 const float* __restrict__ Wq, const float* __restrict__ Wk,
                 const float* __restrict__ Wv, const float* __restrict__ Wo) {
    const int XC = MTOT * EMBED / 4;    // float4 chunks of x
    const int WC = EMBED * EMBED / 4;   // float4 chunks per W
    int i = blockIdx.x * 256 + threadIdx.x;
    float4 v;
    uint2* dst;
    if (i < XC) {
        v = ((const float4*)x)[i];
        dst = (uint2*)g_xh + i;
    } else {
        int j = i - XC;
        int w = j / WC, off = j - w * WC;
        const float* Ws = (w == 0) ? Wq : (w == 1) ? Wk : (w == 2) ? Wv : Wo;
        v = ((const float4*)Ws)[off];
        dst = (uint2*)g_wh + j;
    }
    uint2 p;
    p.x = packh(v.x, v.y);
    p.y = packh(v.z, v.w);
    *dst = p;
}

// ---------------------------------------------------------------------------
// GEMM core: C = gelu(A @ W^T + bias). A,W fp16. Block tile 128x128, 8 warps
// (2m x 4n), warp tile 64x32, BK=32, cp.async double-buffered.
// OHALF: out fp16 [B,H,S,D]; else fp32 flat [M,512].
// ---------------------------------------------------------------------------
template<bool OHALF>
__device__ __forceinline__ void gemm_core(const __half* __restrict__ A,
                                          const __half* __restrict__ W,
                                          const float* __restrict__ bias, void* Cout) {
    __shared__ uint32_t As[2][128][20];
    __shared__ uint32_t Ws[2][128][20];

    const int t    = threadIdx.x;
    const int lane = t & 31;
    const int warp = t >> 5;
    const int wm   = warp >> 2;       // 0..1
    const int wn   = warp & 3;        // 0..3
    const int m0   = blockIdx.y * 128;
    const int n0   = blockIdx.x * 128;
    const int r    = lane >> 2;
    const int cc   = lane & 3;

    const int lrow = t >> 1;          // 0..127
    const int lw   = (t & 1) * 8;     // word offset {0, 8} (16 halves per thread)

    const uint32_t a_loff = (((lane & 15) * 20) + ((lane >> 4) * 4)) * 4;
    const uint32_t b_loff = ((((lane & 7) + ((lane >> 4) * 8)) * 20) + (((lane >> 3) & 1) * 4)) * 4;
    const uint32_t as_w = sptr(&As[0][0][0]) + (uint32_t)(wm * 64 * 20) * 4 + a_loff;
    const uint32_t ws_w = sptr(&Ws[0][0][0]) + (uint32_t)(wn * 32 * 20) * 4 + b_loff;
    const uint32_t BUFB = 128 * 20 * 4;  // buffer stride in bytes

    const __half* abase = A + (size_t)(m0 + lrow) * EMBED + lw * 2;
    const __half* wbase = W + (size_t)(n0 + lrow) * EMBED + lw * 2;
    const uint32_t adst = sptr(&As[0][lrow][lw]);
    const uint32_t wdst = sptr(&Ws[0][lrow][lw]);

    float acc[4][4][4];
    #pragma unroll
    for (int mi = 0; mi < 4; ++mi)
        #pragma unroll
        for (int ni = 0; ni < 4; ++ni)
            #pragma unroll
            for (int j = 0; j < 4; ++j) acc[mi][ni][j] = 0.0f;

    // prologue: issue tile 0
    cpasync16(adst, abase);
    cpasync16(adst + 16, abase + 8);
    cpasync16(wdst, wbase);
    cpasync16(wdst + 16, wbase + 8);
    cp_commit();

    #pragma unroll 1
    for (int i = 0; i < 16; ++i) {
        const int buf = i & 1;
        if (i < 15) {
            const int k0 = (i + 1) * 32;
            const uint32_t boff = (buf ^ 1) * BUFB;
            cpasync16(adst + boff, abase + k0);
            cpasync16(adst + boff + 16, abase + k0 + 8);
            cpasync16(wdst + boff, wbase + k0);
            cpasync16(wdst + boff + 16, wbase + k0 + 8);
            cp_commit();
            cp_wait<1>();
        } else {
            cp_wait<0>();
        }
        __syncthreads();

        const uint32_t aw = as_w + buf * BUFB;
        const uint32_t ww = ws_w + buf * BUFB;
        #pragma unroll
        for (int ks = 0; ks < 2; ++ks) {
            uint32_t a[4][4], b[2][4];
            #pragma unroll
            for (int mi = 0; mi < 4; ++mi)
                ldsm4(a[mi], aw + (uint32_t)(mi * 16 * 20) * 4 + ks * 32);
            #pragma unroll
            for (int np = 0; np < 2; ++np)
                ldsm4(b[np], ww + (uint32_t)(np * 16 * 20) * 4 + ks * 32);
            #pragma unroll
            for (int mi = 0; mi < 4; ++mi)
                #pragma unroll
                for (int np = 0; np < 2; ++np) {
                    mma_f16(acc[mi][2 * np],     a[mi], &b[np][0]);
                    mma_f16(acc[mi][2 * np + 1], a[mi], &b[np][2]);
                }
        }
        __syncthreads();
    }

    // Epilogue: bias + gelu, store
    #pragma unroll
    for (int mi = 0; mi < 4; ++mi) {
        #pragma unroll
        for (int ni = 0; ni < 4; ++ni) {
            int row = m0 + wm * 64 + mi * 16 + r;
            int col = n0 + wn * 32 + ni * 8 + 2 * cc;
            float b0 = bias[col], b1 = bias[col + 1];
            float e00 = gelu_f(acc[mi][ni][0] + b0);
            float e01 = gelu_f(acc[mi][ni][1] + b1);
            float e10 = gelu_f(acc[mi][ni][2] + b0);
            float e11 = gelu_f(acc[mi][ni][3] + b1);
            if (!OHALF) {
                float* C = (float*)Cout;
                float2 v0 = {e00, e01}, v1 = {e10, e11};
                *(float2*)(C + (size_t)row * EMBED + col)       = v0;
                *(float2*)(C + (size_t)(row + 8) * EMBED + col) = v1;
            } else {
                __half* C = (__half*)Cout;
                int bz = row >> 11, s = row & (SEQ - 1);
                int h = col >> 6, d = col & 63;
                *(uint32_t*)&C[(((size_t)(bz * NHEADS + h) * SEQ + s) * HDIM + d)]       = packh(e00, e01);
                *(uint32_t*)&C[(((size_t)(bz * NHEADS + h) * SEQ + (s + 8)) * HDIM + d)] = packh(e10, e11);
            }
        }
    }
}

// Fused Q/K/V projection: blockIdx.z selects which projection.
__global__ __launch_bounds__(256)
void qkv_proj(const float* __restrict__ bq, const float* __restrict__ bk,
              const float* __restrict__ bv) {
    const int z = blockIdx.z;
    const float* bias = (z == 0) ? bq : (z == 1) ? bk : bv;
    __half* C         = (z == 0) ? g_q : (z == 1) ? g_k : g_v;
    gemm_core<true>(g_xh, g_wh + (size_t)z * EMBED * EMBED, bias, C);
}

__global__ __launch_bounds__(256)
void out_proj(const float* __restrict__ bo, float* __restrict__ out) {
    gemm_core<false>(g_o, g_wh + (size_t)3 * EMBED * EMBED, bo, out);
}

// ---------------------------------------------------------------------------
// Flash attention, FP16 mma. Q,K,V: [B*H,S,64] fp16, O: [B,S,E] fp16.
// 128 threads = 4 warps; warp w owns 32 query rows (2 m-frags). KV tile = 64.
// cp.async double-buffered K/V; P stays entirely in registers (QK C-frag
// layout == PV A-frag layout).
// ---------------------------------------------------------------------------
__global__ __launch_bounds__(128)
void flash_mma(const __half* __restrict__ Q, const __half* __restrict__ K,
               const __half* __restrict__ V, __half* __restrict__ O) {
    __shared__ uint32_t sk[2][64][36];    // [buf][kv][dpair]
    __shared__ uint32_t sv[2][64][36];    // [buf][kv][dpair]

    const int t    = threadIdx.x;
    const int lane = t & 31;
    const int w    = t >> 5;
    const int bh   = blockIdx.y;
    const int qt   = blockIdx.x;
    const int r    = lane >> 2;
    const int cc   = lane & 3;

    const uint32_t b_loff = ((((lane & 7) + ((lane >> 4) * 8)) * 36) + (((lane >> 3) & 1) * 4)) * 4;
    const uint32_t t_loff = (((lane & 15) * 36) + ((lane >> 4) * 4)) * 4;
    const uint32_t skb = sptr(&sk[0][0][0]) + b_loff;
    const uint32_t svb = sptr(&sv[0][0][0]) + t_loff;
    const uint32_t BUFB = 64 * 36 * 4;

    const int lrow = t >> 1;          // 0..63
    const int lw16 = (t & 1) * 16;    // word offset {0,16}: 32 halves per thread
    const __half* kbase = K + ((size_t)bh * SEQ + lrow) * HDIM + lw16 * 2;
    const __half* vbase = V + ((size_t)bh * SEQ + lrow) * HDIM + lw16 * 2;
    const uint32_t kdst = sptr(&sk[0][lrow][lw16]);
    const uint32_t vdst = sptr(&sv[0][lrow][lw16]);

    // Q fragments pre-scaled by SC = (1/8)*log2(e)
    const float SC = 0.18033688011112042f;
    const __half2 sc2 = __floats2half2_rn(SC, SC);
    uint32_t qf[2][4][4];
    const __half* qb = Q + ((size_t)bh * SEQ + qt * 128 + w * 32) * HDIM;
    #pragma unroll
    for (int mi = 0; mi < 2; ++mi) {
        #pragma unroll
        for (int kf = 0; kf < 4; ++kf) {
            int row0 = mi * 16 + r;
            uint32_t u0 = *(const uint32_t*)&qb[(size_t)row0 * HDIM + kf * 16 + cc * 2];
            uint32_t u1 = *(const uint32_t*)&qb[(size_t)(row0 + 8) * HDIM + kf * 16 + cc * 2];
            uint32_t u2 = *(const uint32_t*)&qb[(size_t)row0 * HDIM + kf * 16 + 8 + cc * 2];
            uint32_t u3 = *(const uint32_t*)&qb[(size_t)(row0 + 8) * HDIM + kf * 16 + 8 + cc * 2];
            __half2 h0 = __hmul2(*(__half2*)&u0, sc2);
            __half2 h1 = __hmul2(*(__half2*)&u1, sc2);
            __half2 h2 = __hmul2(*(__half2*)&u2, sc2);
            __half2 h3 = __hmul2(*(__half2*)&u3, sc2);
            qf[mi][kf][0] = *(uint32_t*)&h0;
            qf[mi][kf][1] = *(uint32_t*)&h1;
            qf[mi][kf][2] = *(uint32_t*)&h2;
            qf[mi][kf][3] = *(uint32_t*)&h3;
        }
    }

    float o[2][8][4];
    #pragma unroll
    for (int mi = 0; mi < 2; ++mi)
        #pragma unroll
        for (int nf = 0; nf < 8; ++nf)
            #pragma unroll
            for (int j = 0; j < 4; ++j) o[mi][nf][j] = 0.0f;
    float m_i[2][2] = {{-1e30f, -1e30f}, {-1e30f, -1e30f}};   // log2 domain
    float l_i[2][2] = {{0.0f, 0.0f}, {0.0f, 0.0f}};

    // prologue: issue tile 0
    {
        cpasync16(kdst, kbase);
        cpasync16(kdst + 16, kbase + 8);
        cpasync16(kdst + 32, kbase + 16);
        cpasync16(kdst + 48, kbase + 24);
        cpasync16(vdst, vbase);
        cpasync16(vdst + 16, vbase + 8);
        cpasync16(vdst + 32, vbase + 16);
        cpasync16(vdst + 48, vbase + 24);
        cp_commit();
    }

    const int NT = SEQ / 64;
    #pragma unroll 1
    for (int kt = 0; kt < NT; ++kt) {
        const int buf = kt & 1;
        if (kt < NT - 1) {
            const size_t goff = (size_t)(kt + 1) * 64 * HDIM;
            const uint32_t boff = (buf ^ 1) * BUFB;
            cpasync16(kdst + boff, kbase + goff);
            cpasync16(kdst + boff + 16, kbase + goff + 8);
            cpasync16(kdst + boff + 32, kbase + goff + 16);
            cpasync16(kdst + boff + 48, kbase + goff + 24);
            cpasync16(vdst + boff, vbase + goff);
            cpasync16(vdst + boff + 16, vbase + goff + 8);
            cpasync16(vdst + boff + 32, vbase + goff + 16);
            cpasync16(vdst + boff + 48, vbase + goff + 24);
            cp_commit();
            cp_wait<1>();
        } else {
            cp_wait<0>();
        }
        __syncthreads();

        // S = Q @ K^T : 32 q rows x 64 kv cols per warp
        float s[2][8][4];
        #pragma unroll
        for (int mi = 0; mi < 2; ++mi)
            #pragma unroll
            for (int nf = 0; nf < 8; ++nf)
                #pragma unroll
                for (int j = 0; j < 4; ++j) s[mi][nf][j] = 0.0f;

        const uint32_t skw = skb + buf * BUFB;
        #pragma unroll
        for (int kf = 0; kf < 4; ++kf) {
            #pragma unroll
            for (int nfp = 0; nfp < 4; ++nfp) {
                uint32_t bb[4];
                ldsm4(bb, skw + (uint32_t)(nfp * 16 * 36) * 4 + kf * 32);
                #pragma unroll
                for (int mi = 0; mi < 2; ++mi) {
                    mma_f16(s[mi][2 * nfp],     qf[mi][kf], &bb[0]);
                    mma_f16(s[mi][2 * nfp + 1], qf[mi][kf], &bb[2]);
                }
            }
        }

        // Online softmax (log2 domain; scale already folded into Q) + pack P
        uint32_t pf[2][4][4];
        #pragma unroll
        for (int mi = 0; mi < 2; ++mi) {
            float mx0 = -1e30f, mx1 = -1e30f;
            #pragma unroll
            for (int nf = 0; nf < 8; ++nf) {
                mx0 = fmaxf(mx0, fmaxf(s[mi][nf][0], s[mi][nf][1]));
                mx1 = fmaxf(mx1, fmaxf(s[mi][nf][2], s[mi][nf][3]));
            }
            mx0 = fmaxf(mx0, __shfl_xor_sync(0xffffffffu, mx0, 1));
            mx0 = fmaxf(mx0, __shfl_xor_sync(0xffffffffu, mx0, 2));
            mx1 = fmaxf(mx1, __shfl_xor_sync(0xffffffffu, mx1, 1));
            mx1 = fmaxf(mx1, __shfl_xor_sync(0xffffffffu, mx1, 2));

            float mn0 = fmaxf(m_i[mi][0], mx0);
            float mn1 = fmaxf(m_i[mi][1], mx1);
            float corr0 = fexp2(m_i[mi][0] - mn0);
            float corr1 = fexp2(m_i[mi][1] - mn1);

            float rs0 = 0.0f, rs1 = 0.0f;
            #pragma unroll
            for (int nf = 0; nf < 8; ++nf) {
                s[mi][nf][0] = fexp2(s[mi][nf][0] - mn0);
                s[mi][nf][1] = fexp2(s[mi][nf][1] - mn0);
                s[mi][nf][2] = fexp2(s[mi][nf][2] - mn1);
                s[mi][nf][3] = fexp2(s[mi][nf][3] - mn1);
                rs0 += s[mi][nf][0] + s[mi][nf][1];
                rs1 += s[mi][nf][2] + s[mi][nf][3];
            }
            rs0 += __shfl_xor_sync(0xffffffffu, rs0, 1);
            rs0 += __shfl_xor_sync(0xffffffffu, rs0, 2);
            rs1 += __shfl_xor_sync(0xffffffffu, rs1, 1);
            rs1 += __shfl_xor_sync(0xffffffffu, rs1, 2);

            l_i[mi][0] = l_i[mi][0] * corr0 + rs0;
            l_i[mi][1] = l_i[mi][1] * corr1 + rs1;
            m_i[mi][0] = mn0;
            m_i[mi][1] = mn1;

            #pragma unroll
            for (int nf = 0; nf < 8; ++nf) {
                o[mi][nf][0] *= corr0; o[mi][nf][1] *= corr0;
                o[mi][nf][2] *= corr1; o[mi][nf][3] *= corr1;
            }

            // pack P into A-fragments (C-frag of QK == A-frag of PV)
            #pragma unroll
            for (int kf = 0; kf < 4; ++kf) {
                pf[mi][kf][0] = packh(s[mi][2 * kf][0],     s[mi][2 * kf][1]);
                pf[mi][kf][1] = packh(s[mi][2 * kf][2],     s[mi][2 * kf][3]);
                pf[mi][kf][2] = packh(s[mi][2 * kf + 1][0], s[mi][2 * kf + 1][1]);
                pf[mi][kf][3] = packh(s[mi][2 * kf + 1][2], s[mi][2 * kf + 1][3]);
            }
        }

        // O += P @ V  (row-major V tile, B-frags via ldmatrix.trans)
        const uint32_t svw = svb + buf * BUFB;
        #pragma unroll
        for (int kf = 0; kf < 4; ++kf) {
            #pragma unroll
            for (int nfp = 0; nfp < 4; ++nfp) {
                uint32_t bb[4];
                ldsm4t(bb, svw + (uint32_t)(kf * 16 * 36) * 4 + nfp * 32);
                #pragma unroll
                for (int mi = 0; mi < 2; ++mi) {
                    mma_f16(o[mi][2 * nfp],     pf[mi][kf], &bb[0]);
                    mma_f16(o[mi][2 * nfp + 1], pf[mi][kf], &bb[2]);
                }
            }
        }
        __syncthreads();   // all warps done with this buffer before it is refilled
    }

    // Normalize + store fp16 into [B, S, E]
    int bz = bh >> 3, h = bh & 7;
    #pragma unroll
    for (int mi = 0; mi < 2; ++mi) {
        float inv0 = 1.0f / l_i[mi][0];
        float inv1 = 1.0f / l_i[mi][1];
        int row0 = qt * 128 + w * 32 + mi * 16 + r;
        __half* op0 = O + ((size_t)bz * SEQ + row0) * EMBED + h * HDIM;
        __half* op1 = O + ((size_t)bz * SEQ + row0 + 8) * EMBED + h * HDIM;
        #pragma unroll
        for (int nf = 0; nf < 8; ++nf) {
            *(uint32_t*)(op0 + nf * 8 + 2 * cc) = packh(o[mi][nf][0] * inv0, o[mi][nf][1] * inv0);
            *(uint32_t*)(op1 + nf * 8 + 2 * cc) = packh(o[mi][nf][2] * inv1, o[mi][nf][3] * inv1);
        }
    }
}

extern "C" void kernel_launch(void* const* d_in, const int* in_sizes, int n_in,
                              void* d_out, int out_size) {
    const float* x  = (const float*)d_in[0];
    const float* Wq = (const float*)d_in[1];
    const float* bq = (const float*)d_in[2];
    const float* Wk = (const float*)d_in[3];
    const float* bk = (const float*)d_in[4];
    const float* Wv = (const float*)d_in[5];
    const float* bv = (const float*)d_in[6];
    const float* Wo = (const float*)d_in[7];
    const float* bo = (const float*)d_in[8];
    float* out = (float*)d_out;

    __half *gq, *gk, *gv, *go;
    cudaGetSymbolAddress((void**)&gq, g_q);
    cudaGetSymbolAddress((void**)&gk, g_k);
    cudaGetSymbolAddress((void**)&gv, g_v);
    cudaGetSymbolAddress((void**)&go, g_o);

    const int XC = MTOT * EMBED / 4;
    const int WC = EMBED * EMBED / 4;
    convert_f2h<<<(XC + 4 * WC) / 256, 256>>>(x, Wq, Wk, Wv, Wo);

    dim3 gridP(EMBED / 128, MTOT / 128, 3);   // (4, 64, 3)
    qkv_proj<<<gridP, 256>>>(bq, bk, bv);

    dim3 gridA(SEQ / 128, BATCH * NHEADS);    // (16, 32)
    flash_mma<<<gridA, 128>>>(gq, gk, gv, go);

    dim3 gridO(EMBED / 128, MTOT / 128);      // (4, 64)
    out_proj<<<gridO, 256>>>(bo, out);
}